// round 1
// baseline (speedup 1.0000x reference)
#include <cuda_runtime.h>
#include <math.h>

// ---------------------------------------------------------------------------
// MultiScaleCrossAttn — fp32 baseline
// Scales: df={16,4,7} -> grids 14x14 / 56x56 / 32x32, d=96, heads=3 (hd=32)
// ---------------------------------------------------------------------------

#define ROWS0 12544      // 64*14*14
#define ROWS1 200704     // 64*56*56
#define ROWS2 65536      // 64*32*32
#define KVROWS 313600    // 64*196*25

// scratch (device globals; no allocation allowed)
__device__ float g_t0[ROWS0 * 96];
__device__ float g_t1[ROWS1 * 96];
__device__ float g_t2[ROWS2 * 96];
__device__ float g_qkv[ROWS1 * 288];
__device__ float g_ob[ROWS1 * 96];     // attn-out / ff-hidden scratch
__device__ float g_kv[KVROWS * 96];    // LN'd neighbor rows
__device__ float g_k[KVROWS * 96];
__device__ float g_v[KVROWS * 96];
__device__ float g_q[ROWS0 * 96];
__device__ float g_co[ROWS0 * 96];

// ---------------------------------------------------------------------------
// patch merge: out[token, 96] = gather(patch)[F] @ W[F,96] + b
// feature order f = (c*DF + ki)*DF + kj  (torch unfold order)
// ---------------------------------------------------------------------------
template <int DF, int F, int WOUT, int TB>
__global__ __launch_bounds__(96) void patch_k(const float* __restrict__ x,
                                              const float* __restrict__ w,
                                              const float* __restrict__ bias,
                                              float* __restrict__ out) {
    extern __shared__ float sp[];  // TB * F
    const int t = threadIdx.x;
    const int tok0 = blockIdx.x * TB;
    const int T = WOUT * WOUT;

    for (int idx = t; idx < TB * F; idx += 96) {
        int tb = idx / F, f = idx % F;
        int tok = tok0 + tb;
        int b = tok / T, hw = tok % T;
        int h = hw / WOUT, ww = hw % WOUT;
        int c = f / (DF * DF), rem = f % (DF * DF);
        int ki = rem / DF, kj = rem % DF;
        sp[idx] = x[((b * 3 + c) * 224 + h * DF + ki) * 224 + ww * DF + kj];
    }
    __syncthreads();

    float acc[TB];
#pragma unroll
    for (int tb = 0; tb < TB; ++tb) acc[tb] = 0.f;

#pragma unroll 4
    for (int f = 0; f < F; ++f) {
        float wv = __ldg(&w[f * 96 + t]);
#pragma unroll
        for (int tb = 0; tb < TB; ++tb) acc[tb] = fmaf(sp[tb * F + f], wv, acc[tb]);
    }
    float bv = bias[t];
#pragma unroll
    for (int tb = 0; tb < TB; ++tb) out[(tok0 + tb) * 96 + t] = acc[tb] + bv;
}

// ---------------------------------------------------------------------------
// generic 96-in matmul, 96 threads (one output column each, CPT=N/96 cols),
// TB rows register-blocked. Optional fused LN on input rows, fused GELU,
// epilogues: 0 = store, 1 = out += , 2 = out = res + val
// ---------------------------------------------------------------------------
template <int N, int TB, bool LNF, bool GELU, int EPI>
__global__ __launch_bounds__(96) void mm_k(const float* __restrict__ x,
                                           const float* __restrict__ W,
                                           const float* __restrict__ bias,
                                           const float* __restrict__ lng,
                                           const float* __restrict__ lnb,
                                           const float* __restrict__ res,
                                           float* __restrict__ out) {
    constexpr int CPT = N / 96;
    __shared__ float xs[TB][96];
    __shared__ float red[2][3];
    const int t = threadIdx.x;
    const int warp = t >> 5, lane = t & 31;
    const int row0 = blockIdx.x * TB;

    for (int tb = 0; tb < TB; ++tb) {
        float v = x[(row0 + tb) * 96 + t];
        if (LNF) {
            float s = v, s2 = v * v;
#pragma unroll
            for (int o = 16; o > 0; o >>= 1) {
                s += __shfl_xor_sync(0xffffffffu, s, o);
                s2 += __shfl_xor_sync(0xffffffffu, s2, o);
            }
            if (lane == 0) { red[0][warp] = s; red[1][warp] = s2; }
            __syncthreads();
            float S = red[0][0] + red[0][1] + red[0][2];
            float S2 = red[1][0] + red[1][1] + red[1][2];
            float mean = S * (1.f / 96.f);
            float var = fmaf(-mean, mean, S2 * (1.f / 96.f));
            v = (v - mean) * rsqrtf(var + 1e-5f) * lng[t] + lnb[t];
            __syncthreads();
        }
        xs[tb][t] = v;
    }
    __syncthreads();

    float acc[TB][CPT];
#pragma unroll
    for (int tb = 0; tb < TB; ++tb)
#pragma unroll
        for (int c = 0; c < CPT; ++c) acc[tb][c] = 0.f;

#pragma unroll 4
    for (int k = 0; k < 96; ++k) {
        float wv[CPT];
#pragma unroll
        for (int c = 0; c < CPT; ++c) wv[c] = __ldg(&W[k * N + t + 96 * c]);
#pragma unroll
        for (int tb = 0; tb < TB; ++tb) {
            float xv = xs[tb][k];
#pragma unroll
            for (int c = 0; c < CPT; ++c) acc[tb][c] = fmaf(xv, wv[c], acc[tb][c]);
        }
    }

#pragma unroll
    for (int tb = 0; tb < TB; ++tb) {
        int row = row0 + tb;
#pragma unroll
        for (int c = 0; c < CPT; ++c) {
            float val = acc[tb][c] + (bias ? bias[t + 96 * c] : 0.f);
            if (GELU) val = 0.5f * val * (1.f + erff(val * 0.70710678118654752f));
            int oi = row * N + t + 96 * c;
            if constexpr (EPI == 0) out[oi] = val;
            else if constexpr (EPI == 1) out[oi] += val;
            else out[oi] = res[row * 96 + t] + val;
        }
    }
}

// ---------------------------------------------------------------------------
// window attention: one block per (batch, window), 3 heads serial, hd=32
// qkv rows: [r,288] = q|k|v ; window token r from spatial decomposition
// ---------------------------------------------------------------------------
template <int WS>
__global__ __launch_bounds__(128) void win_attn_k(const float* __restrict__ qkv,
                                                  float* __restrict__ o,
                                                  int Wout, int nw) {
    constexpr int NT = WS * WS;
    __shared__ float sq[NT][33], sk[NT][33], sv[NT][33];
    __shared__ float sS[NT * NT];
    const int b = blockIdx.x / (nw * nw);
    const int win = blockIdx.x % (nw * nw);
    const int wr = win / nw, wc = win % nw;
    const int t = threadIdx.x;
    const int T = Wout * Wout;
    const float scale = 0.17677669529663687f;  // 1/sqrt(32)

    for (int head = 0; head < 3; ++head) {
        for (int idx = t; idx < NT * 32; idx += 128) {
            int p = idx >> 5, c = idx & 31;
            int wi = p / WS, wj = p % WS;
            int r = b * T + (wr * WS + wi) * Wout + wc * WS + wj;
            const float* base = qkv + r * 288 + head * 32 + c;
            sq[p][c] = base[0];
            sk[p][c] = base[96];
            sv[p][c] = base[192];
        }
        __syncthreads();
        for (int idx = t; idx < NT * NT; idx += 128) {
            int i = idx / NT, j = idx % NT;
            float s = 0.f;
#pragma unroll
            for (int c = 0; c < 32; ++c) s = fmaf(sq[i][c], sk[j][c], s);
            sS[idx] = s * scale;
        }
        __syncthreads();
        if (t < NT) {
            float m = -1e30f;
            for (int j = 0; j < NT; ++j) m = fmaxf(m, sS[t * NT + j]);
            float Z = 0.f;
            for (int j = 0; j < NT; ++j) {
                float e = __expf(sS[t * NT + j] - m);
                sS[t * NT + j] = e;
                Z += e;
            }
            float inv = 1.f / Z;
            for (int j = 0; j < NT; ++j) sS[t * NT + j] *= inv;
        }
        __syncthreads();
        for (int idx = t; idx < NT * 32; idx += 128) {
            int i = idx >> 5, c = idx & 31;
            float acc = 0.f;
            for (int j = 0; j < NT; ++j) acc = fmaf(sS[i * NT + j], sv[j][c], acc);
            int wi = i / WS, wj = i % WS;
            int r = b * T + (wr * WS + wi) * Wout + wc * WS + wj;
            o[r * 96 + head * 32 + c] = acc;
        }
        __syncthreads();
    }
}

// ---------------------------------------------------------------------------
// neighbor gather + LN. Reproduces the reference's scrambled reshape:
// kv[b,l,k,c2] with F = k*96+c2, c = F//(s*s), rem = F%(s*s), ki=rem/s, kj=rem%s
// scale1: s=4 no pad (from 56x56); scale2: s=3, pad 5 each side (from 32x32)
// ---------------------------------------------------------------------------
__global__ __launch_bounds__(96) void gather_ln_k(const float* __restrict__ t1,
                                                  const float* __restrict__ t2,
                                                  const float* __restrict__ g,
                                                  const float* __restrict__ bb,
                                                  float* __restrict__ kv) {
    const int b = blockIdx.x / 196, l = blockIdx.x % 196;
    const int i1 = l / 14, j1 = l % 14;
    __shared__ float s1[16 * 97];
    __shared__ float s2[9 * 97];
    __shared__ float red[2][3];
    const int t = threadIdx.x, warp = t >> 5, lane = t & 31;

    for (int p = 0; p < 16; ++p) {
        int ki = p >> 2, kj = p & 3;
        s1[p * 97 + t] = t1[((b * 56 + i1 * 4 + ki) * 56 + j1 * 4 + kj) * 96 + t];
    }
    for (int p = 0; p < 9; ++p) {
        int ki = p / 3, kj = p % 3;
        int rr = i1 * 3 + ki - 5, cc = j1 * 3 + kj - 5;
        float v = 0.f;
        if (rr >= 0 && rr < 32 && cc >= 0 && cc < 32)
            v = t2[((b * 32 + rr) * 32 + cc) * 96 + t];
        s2[p * 97 + t] = v;
    }
    __syncthreads();
    const float gg = g[t], bv = bb[t];

    for (int k = 0; k < 25; ++k) {
        float v;
        if (k < 16) {
            int F = k * 96 + t;
            int c = F >> 4, rem = F & 15;
            v = s1[rem * 97 + c];
        } else {
            int F = (k - 16) * 96 + t;
            int c = F / 9, rem = F % 9;
            v = s2[rem * 97 + c];
        }
        float s = v, s2s = v * v;
#pragma unroll
        for (int o = 16; o > 0; o >>= 1) {
            s += __shfl_xor_sync(0xffffffffu, s, o);
            s2s += __shfl_xor_sync(0xffffffffu, s2s, o);
        }
        if (lane == 0) { red[0][warp] = s; red[1][warp] = s2s; }
        __syncthreads();
        float S = red[0][0] + red[0][1] + red[0][2];
        float S2 = red[1][0] + red[1][1] + red[1][2];
        float mean = S * (1.f / 96.f);
        float var = fmaf(-mean, mean, S2 * (1.f / 96.f));
        kv[(blockIdx.x * 25 + k) * 96 + t] = (v - mean) * rsqrtf(var + 1e-5f) * gg + bv;
        __syncthreads();
    }
}

// ---------------------------------------------------------------------------
// cross attention: 1 query vs 25 keys, full d=96 (single head), scale 1/sqrt(96)
// one block per (b,l), 96 threads
// ---------------------------------------------------------------------------
__global__ __launch_bounds__(96) void cross_attn_k(const float* __restrict__ q,
                                                   const float* __restrict__ kbuf,
                                                   const float* __restrict__ vbuf,
                                                   float* __restrict__ o) {
    const int rl = blockIdx.x;
    __shared__ float sk[25][97], sv[25][97], sq[96], ss[25];
    const int t = threadIdx.x;
    sq[t] = q[rl * 96 + t];
    for (int k = 0; k < 25; ++k) {
        sk[k][t] = kbuf[(rl * 25 + k) * 96 + t];
        sv[k][t] = vbuf[(rl * 25 + k) * 96 + t];
    }
    __syncthreads();
    if (t < 25) {
        float s = 0.f;
        for (int c = 0; c < 96; ++c) s = fmaf(sq[c], sk[t][c], s);
        ss[t] = s * 0.10206207261596575f;  // 1/sqrt(96)
    }
    __syncthreads();
    float m = -1e30f;
#pragma unroll
    for (int k = 0; k < 25; ++k) m = fmaxf(m, ss[k]);
    float Z = 0.f, acc = 0.f;
#pragma unroll
    for (int k = 0; k < 25; ++k) {
        float e = __expf(ss[k] - m);
        Z += e;
        acc = fmaf(e, sv[k][t], acc);
    }
    o[rl * 96 + t] = acc / Z;
}

// ---------------------------------------------------------------------------
extern "C" void kernel_launch(void* const* d_in, const int* in_sizes, int n_in,
                              void* d_out, int out_size) {
    const float* x       = (const float*)d_in[0];
    const float* pw[3]   = {(const float*)d_in[1], (const float*)d_in[3], (const float*)d_in[5]};
    const float* pb[3]   = {(const float*)d_in[2], (const float*)d_in[4], (const float*)d_in[6]};
    const float* wa_ln_g = (const float*)d_in[7];
    const float* wa_ln_b = (const float*)d_in[8];
    const float* wa_qkv  = (const float*)d_in[9];
    const float* wa_ow   = (const float*)d_in[10];
    const float* wa_ob   = (const float*)d_in[11];
    const float* ff_ln_g = (const float*)d_in[12];
    const float* ff_ln_b = (const float*)d_in[13];
    const float* ff_w1   = (const float*)d_in[14];
    const float* ff_b1   = (const float*)d_in[15];
    const float* ff_w2   = (const float*)d_in[16];
    const float* ff_b2   = (const float*)d_in[17];
    const float* lnn_g   = (const float*)d_in[18];
    const float* lnn_b   = (const float*)d_in[19];
    const float* ca_wq   = (const float*)d_in[20];
    const float* ca_wk   = (const float*)d_in[21];
    const float* ca_wv   = (const float*)d_in[22];
    const float* ca_wo   = (const float*)d_in[23];
    const float* ca_bo   = (const float*)d_in[24];
    const float* fi_ln_g = (const float*)d_in[25];
    const float* fi_ln_b = (const float*)d_in[26];
    const float* fi_w1   = (const float*)d_in[27];
    const float* fi_b1   = (const float*)d_in[28];
    const float* fi_w2   = (const float*)d_in[29];
    const float* fi_b2   = (const float*)d_in[30];
    float* out = (float*)d_out;

    float *t0, *t1, *t2, *qkv, *ob, *kv, *kk, *vv, *qq, *co;
    cudaGetSymbolAddress((void**)&t0, g_t0);
    cudaGetSymbolAddress((void**)&t1, g_t1);
    cudaGetSymbolAddress((void**)&t2, g_t2);
    cudaGetSymbolAddress((void**)&qkv, g_qkv);
    cudaGetSymbolAddress((void**)&ob, g_ob);
    cudaGetSymbolAddress((void**)&kv, g_kv);
    cudaGetSymbolAddress((void**)&kk, g_k);
    cudaGetSymbolAddress((void**)&vv, g_v);
    cudaGetSymbolAddress((void**)&qq, g_q);
    cudaGetSymbolAddress((void**)&co, g_co);

    // patch merges
    patch_k<16, 768, 14, 16><<<ROWS0 / 16, 96, 16 * 768 * 4>>>(x, pw[0], pb[0], t0);
    patch_k<4, 48, 56, 16><<<ROWS1 / 16, 96, 16 * 48 * 4>>>(x, pw[1], pb[1], t1);
    patch_k<7, 147, 32, 16><<<ROWS2 / 16, 96, 16 * 147 * 4>>>(x, pw[2], pb[2], t2);

    const int rows[3] = {ROWS0, ROWS1, ROWS2};
    float* tb[3] = {t0, t1, t2};
    for (int i = 0; i < 3; ++i) {
        const int R = rows[i];
        float* t = tb[i];
        // qkv = LN(t) @ Wqkv  (no bias)
        mm_k<288, 16, true, false, 0><<<R / 16, 96>>>(
            t, wa_qkv + i * 96 * 288, nullptr, wa_ln_g + i * 96, wa_ln_b + i * 96, nullptr, qkv);
        if (i == 0)      win_attn_k<7><<<64 * 2 * 2, 128>>>(qkv, ob, 14, 2);
        else if (i == 1) win_attn_k<4><<<64 * 14 * 14, 128>>>(qkv, ob, 56, 14);
        else             win_attn_k<4><<<64 * 8 * 8, 128>>>(qkv, ob, 32, 8);
        // t += attn_out @ Wo + bo
        mm_k<96, 32, false, false, 1><<<R / 32, 96>>>(
            ob, wa_ow + i * 9216, wa_ob + i * 96, nullptr, nullptr, nullptr, t);
        // h = gelu(LN(t) @ W1 + b1)
        mm_k<96, 32, true, true, 0><<<R / 32, 96>>>(
            t, ff_w1 + i * 9216, ff_b1 + i * 96, ff_ln_g + i * 96, ff_ln_b + i * 96, nullptr, ob);
        // t += h @ W2 + b2
        mm_k<96, 32, false, false, 1><<<R / 32, 96>>>(
            ob, ff_w2 + i * 9216, ff_b2 + i * 96, nullptr, nullptr, nullptr, t);
    }

    // neighbor gather + LN -> kv[64*196*25, 96]
    gather_ln_k<<<64 * 196, 96>>>(t1, t2, lnn_g, lnn_b, kv);
    // k / v projections (inputs already LN'd)
    mm_k<96, 32, false, false, 0><<<KVROWS / 32, 96>>>(kv, ca_wk, nullptr, nullptr, nullptr, nullptr, kk);
    mm_k<96, 32, false, false, 0><<<KVROWS / 32, 96>>>(kv, ca_wv, nullptr, nullptr, nullptr, nullptr, vv);
    // q = LN(x1) @ Wq
    mm_k<96, 32, true, false, 0><<<ROWS0 / 32, 96>>>(t0, ca_wq, nullptr, lnn_g, lnn_b, nullptr, qq);
    // cross attention
    cross_attn_k<<<ROWS0 / 96 * 96 ? 12544 : 12544, 96>>>(qq, kk, vv, co);
    // out = x1 + o @ Wo + bo
    mm_k<96, 32, false, false, 2><<<ROWS0 / 32, 96>>>(co, ca_wo, ca_bo, nullptr, nullptr, t0, out);
    // out += gelu(LN(out) @ w1 + b1) @ w2 + b2
    mm_k<96, 32, true, true, 0><<<ROWS0 / 32, 96>>>(out, fi_w1, fi_b1, fi_ln_g, fi_ln_b, nullptr, co);
    mm_k<96, 32, false, false, 1><<<ROWS0 / 32, 96>>>(co, fi_w2, fi_b2, nullptr, nullptr, nullptr, out);
}

// round 2
// speedup vs baseline: 1.4391x; 1.4391x over previous
#include <cuda_runtime.h>
#include <math.h>

// ---------------------------------------------------------------------------
// MultiScaleCrossAttn — tf32 tensor-core GEMMs + fused LN/GELU/residual
// Scales: df={16,4,7} -> grids 14x14 / 56x56 / 32x32, d=96, heads=3 (hd=32)
// ---------------------------------------------------------------------------

#define ROWS0 12544      // 64*14*14
#define ROWS1 200704     // 64*56*56
#define ROWS2 65536      // 64*32*32
#define KVROWS 313600    // 64*196*25

// scratch (device globals; no allocation allowed)
__device__ float g_t0[ROWS0 * 96];
__device__ float g_t1[ROWS1 * 96];
__device__ float g_t2[ROWS2 * 96];
__device__ float g_qkv[ROWS1 * 288];
__device__ float g_ob[ROWS1 * 96];     // attn-out / ff-hidden scratch
__device__ float g_kv[KVROWS * 96];    // LN'd neighbor rows
__device__ float g_k[KVROWS * 96];
__device__ float g_v[KVROWS * 96];
__device__ float g_q[ROWS0 * 96];
__device__ float g_co[ROWS0 * 96];

// ---------------------------------------------------------------------------
// tf32 helpers
// ---------------------------------------------------------------------------
__device__ __forceinline__ unsigned f2tf(float f) {
    unsigned u;
    asm("cvt.rna.tf32.f32 %0, %1;" : "=r"(u) : "f"(f));
    return u;
}

__device__ __forceinline__ void mma8(float c[4],
                                     unsigned a0, unsigned a1, unsigned a2, unsigned a3,
                                     unsigned b0, unsigned b1) {
    asm volatile(
        "mma.sync.aligned.m16n8k8.row.col.f32.tf32.tf32.f32 "
        "{%0,%1,%2,%3}, {%4,%5,%6,%7}, {%8,%9}, {%0,%1,%2,%3};\n"
        : "+f"(c[0]), "+f"(c[1]), "+f"(c[2]), "+f"(c[3])
        : "r"(a0), "r"(a1), "r"(a2), "r"(a3), "r"(b0), "r"(b1));
}

// ---------------------------------------------------------------------------
// generic K=96 row-GEMM on tensor cores.
// block: 128 thr, tile 64 rows x 96 cols; blockIdx.y = 96-col chunk (ldw = N)
// A rows optionally LayerNorm'd (fp32) then tf32-converted into frag-order smem.
// epilogues: 0 = store, 1 = out += , 2 = out = res + val ; optional GELU, bias.
// ---------------------------------------------------------------------------
template <bool LNF, bool GELU, int EPI>
__global__ __launch_bounds__(128) void gemm_tc(const float* __restrict__ A,
                                               const float* __restrict__ W,
                                               const float* __restrict__ bias,
                                               const float* __restrict__ lng,
                                               const float* __restrict__ lnb,
                                               const float* __restrict__ res,
                                               float* __restrict__ out, int ldw) {
    __shared__ unsigned As[12 * 4 * 4 * 32];  // [ktile][mtile][reg][lane]
    const int tid = threadIdx.x;
    const int lane = tid & 31, warp = tid >> 5;
    const int row0 = blockIdx.x * 64;
    const int ncol0 = blockIdx.y * 96;

    // ---- load (+LN) + tf32 convert: 2 threads per row ----
    {
        const int row = tid >> 1, sub = tid & 1;
        const float* ap = A + (row0 + row) * 96;
        float4 vals[12];
#pragma unroll
        for (int j = 0; j < 12; ++j)
            vals[j] = __ldg((const float4*)(ap + (sub * 12 + j) * 4));
        float mean = 0.f, rstd = 0.f;
        if (LNF) {
            float s = 0.f, s2 = 0.f;
#pragma unroll
            for (int j = 0; j < 12; ++j) {
                float4 v = vals[j];
                s += v.x + v.y + v.z + v.w;
                s2 += v.x * v.x + v.y * v.y + v.z * v.z + v.w * v.w;
            }
            s += __shfl_xor_sync(0xffffffffu, s, 1);
            s2 += __shfl_xor_sync(0xffffffffu, s2, 1);
            mean = s * (1.f / 96.f);
            float var = fmaf(-mean, mean, s2 * (1.f / 96.f));
            rstd = rsqrtf(var + 1e-5f);
        }
        const int r = row & 15, mt = row >> 4;
#pragma unroll
        for (int j = 0; j < 12; ++j) {
            int k0 = (sub * 12 + j) * 4;
            float4 v = vals[j];
            if (LNF) {
                float4 g = __ldg((const float4*)(lng + k0));
                float4 bb = __ldg((const float4*)(lnb + k0));
                v.x = (v.x - mean) * rstd * g.x + bb.x;
                v.y = (v.y - mean) * rstd * g.y + bb.y;
                v.z = (v.z - mean) * rstd * g.z + bb.z;
                v.w = (v.w - mean) * rstd * g.w + bb.w;
            }
            int ktile = k0 >> 3;
            int i = (((k0 >> 2) & 1) << 1) | (r >> 3);
            int addr = ((ktile * 4 + mt) * 4 + i) * 32 + ((r & 7) << 2);
            uint4 u;
            u.x = f2tf(v.x); u.y = f2tf(v.y); u.z = f2tf(v.z); u.w = f2tf(v.w);
            *(uint4*)&As[addr] = u;
        }
    }
    __syncthreads();

    // ---- mma mainloop: 12 k-steps of 8 ----
    float acc[4][3][4];
#pragma unroll
    for (int mt = 0; mt < 4; ++mt)
#pragma unroll
        for (int j = 0; j < 3; ++j)
#pragma unroll
            for (int i = 0; i < 4; ++i) acc[mt][j][i] = 0.f;

    const int tig = lane & 3, gid = lane >> 2;
    const float* Wp = W + ncol0 + warp * 24 + gid;

#pragma unroll
    for (int kt = 0; kt < 12; ++kt) {
        unsigned b[3][2];
#pragma unroll
        for (int j = 0; j < 3; ++j) {
            const float* wp = Wp + j * 8 + (kt * 8 + tig) * ldw;
            b[j][0] = f2tf(__ldg(wp));
            b[j][1] = f2tf(__ldg(wp + 4 * ldw));
        }
        unsigned a[4][4];
#pragma unroll
        for (int mt = 0; mt < 4; ++mt)
#pragma unroll
            for (int i = 0; i < 4; ++i)
                a[mt][i] = As[((kt * 4 + mt) * 4 + i) * 32 + lane];
#pragma unroll
        for (int mt = 0; mt < 4; ++mt)
#pragma unroll
            for (int j = 0; j < 3; ++j)
                mma8(acc[mt][j], a[mt][0], a[mt][1], a[mt][2], a[mt][3], b[j][0], b[j][1]);
    }

    // ---- epilogue ----
#pragma unroll
    for (int mt = 0; mt < 4; ++mt) {
#pragma unroll
        for (int j = 0; j < 3; ++j) {
            int nc = ncol0 + warp * 24 + j * 8 + 2 * tig;
#pragma unroll
            for (int i = 0; i < 4; ++i) {
                int rr = row0 + mt * 16 + gid + ((i >> 1) ? 8 : 0);
                int cc = nc + (i & 1);
                float val = acc[mt][j][i] + (bias ? __ldg(bias + cc) : 0.f);
                if (GELU) val = 0.5f * val * (1.f + erff(val * 0.70710678118654752f));
                int oi = rr * ldw + cc;
                if constexpr (EPI == 0) out[oi] = val;
                else if constexpr (EPI == 1) out[oi] += val;
                else out[oi] = res[rr * 96 + cc] + val;
            }
        }
    }
}

// ---------------------------------------------------------------------------
// patch merge on tensor cores: gather unfold features -> tf32 frag smem -> mma
// K chunked by 96 (KPAD = KTOT rounded up to 8). N=96, bias, EPI=0.
// ---------------------------------------------------------------------------
template <int DF, int KTOT, int WOUT>
__global__ __launch_bounds__(128) void patch_tc(const float* __restrict__ x,
                                                const float* __restrict__ w,
                                                const float* __restrict__ bias,
                                                float* __restrict__ out) {
    constexpr int KPAD = (KTOT + 7) & ~7;
    __shared__ unsigned As[12 * 4 * 4 * 32];
    const int tid = threadIdx.x, lane = tid & 31, warp = tid >> 5;
    const int row0 = blockIdx.x * 64;
    const int T = WOUT * WOUT;
    const int tig = lane & 3, gid = lane >> 2;

    float acc[4][3][4];
#pragma unroll
    for (int mt = 0; mt < 4; ++mt)
#pragma unroll
        for (int j = 0; j < 3; ++j)
#pragma unroll
            for (int i = 0; i < 4; ++i) acc[mt][j][i] = 0.f;

    for (int kc = 0; kc < KPAD; kc += 96) {
        const int cl = (KPAD - kc) < 96 ? (KPAD - kc) : 96;
        // gather + convert into frag-order smem
        for (int idx = tid; idx < 64 * cl; idx += 128) {
            int rrow = idx / cl, dk = idx - rrow * cl;
            int f = kc + dk;
            float v = 0.f;
            if (f < KTOT) {
                int tok = row0 + rrow;
                int b = tok / T, hw = tok - b * T;
                int h = hw / WOUT, ww = hw - h * WOUT;
                int c = f / (DF * DF), rem = f - c * DF * DF;
                int ki = rem / DF, kj = rem - ki * DF;
                v = __ldg(&x[((b * 3 + c) * 224 + h * DF + ki) * 224 + ww * DF + kj]);
            }
            int r = rrow & 15, mt = rrow >> 4;
            int ktile = dk >> 3;
            int i = (((dk >> 2) & 1) << 1) | (r >> 3);
            As[((ktile * 4 + mt) * 4 + i) * 32 + ((r & 7) << 2) + (dk & 3)] = f2tf(v);
        }
        __syncthreads();

        const int ks = cl >> 3;
#pragma unroll 2
        for (int kt = 0; kt < ks; ++kt) {
            unsigned b2[3][2];
#pragma unroll
            for (int j = 0; j < 3; ++j) {
                int kr = kc + kt * 8 + tig;
                const float* wp = w + warp * 24 + gid + j * 8;
                b2[j][0] = (kr < KTOT) ? f2tf(__ldg(wp + kr * 96)) : 0u;
                b2[j][1] = (kr + 4 < KTOT) ? f2tf(__ldg(wp + (kr + 4) * 96)) : 0u;
            }
            unsigned a[4][4];
#pragma unroll
            for (int mt = 0; mt < 4; ++mt)
#pragma unroll
                for (int i = 0; i < 4; ++i)
                    a[mt][i] = As[((kt * 4 + mt) * 4 + i) * 32 + lane];
#pragma unroll
            for (int mt = 0; mt < 4; ++mt)
#pragma unroll
                for (int j = 0; j < 3; ++j)
                    mma8(acc[mt][j], a[mt][0], a[mt][1], a[mt][2], a[mt][3], b2[j][0], b2[j][1]);
        }
        __syncthreads();
    }

#pragma unroll
    for (int mt = 0; mt < 4; ++mt) {
#pragma unroll
        for (int j = 0; j < 3; ++j) {
            int nc = warp * 24 + j * 8 + 2 * tig;
#pragma unroll
            for (int i = 0; i < 4; ++i) {
                int rr = row0 + mt * 16 + gid + ((i >> 1) ? 8 : 0);
                int cc = nc + (i & 1);
                out[rr * 96 + cc] = acc[mt][j][i] + __ldg(bias + cc);
            }
        }
    }
}

// ---------------------------------------------------------------------------
// window attention: one block per (batch, window), 3 heads serial, hd=32
// ---------------------------------------------------------------------------
template <int WS>
__global__ __launch_bounds__(128) void win_attn_k(const float* __restrict__ qkv,
                                                  float* __restrict__ o,
                                                  int Wout, int nw) {
    constexpr int NT = WS * WS;
    __shared__ float sq[NT][33], sk[NT][33], sv[NT][33];
    __shared__ float sS[NT * NT];
    const int b = blockIdx.x / (nw * nw);
    const int win = blockIdx.x % (nw * nw);
    const int wr = win / nw, wc = win % nw;
    const int t = threadIdx.x;
    const int T = Wout * Wout;
    const float scale = 0.17677669529663687f;  // 1/sqrt(32)

    for (int head = 0; head < 3; ++head) {
        for (int idx = t; idx < NT * 32; idx += 128) {
            int p = idx >> 5, c = idx & 31;
            int wi = p / WS, wj = p % WS;
            int r = b * T + (wr * WS + wi) * Wout + wc * WS + wj;
            const float* base = qkv + r * 288 + head * 32 + c;
            sq[p][c] = base[0];
            sk[p][c] = base[96];
            sv[p][c] = base[192];
        }
        __syncthreads();
        for (int idx = t; idx < NT * NT; idx += 128) {
            int i = idx / NT, j = idx % NT;
            float s = 0.f;
#pragma unroll
            for (int c = 0; c < 32; ++c) s = fmaf(sq[i][c], sk[j][c], s);
            sS[idx] = s * scale;
        }
        __syncthreads();
        if (t < NT) {
            float m = -1e30f;
            for (int j = 0; j < NT; ++j) m = fmaxf(m, sS[t * NT + j]);
            float Z = 0.f;
            for (int j = 0; j < NT; ++j) {
                float e = __expf(sS[t * NT + j] - m);
                sS[t * NT + j] = e;
                Z += e;
            }
            float inv = 1.f / Z;
            for (int j = 0; j < NT; ++j) sS[t * NT + j] *= inv;
        }
        __syncthreads();
        for (int idx = t; idx < NT * 32; idx += 128) {
            int i = idx >> 5, c = idx & 31;
            float acc = 0.f;
            for (int j = 0; j < NT; ++j) acc = fmaf(sS[i * NT + j], sv[j][c], acc);
            int wi = i / WS, wj = i % WS;
            int r = b * T + (wr * WS + wi) * Wout + wc * WS + wj;
            o[r * 96 + head * 32 + c] = acc;
        }
        __syncthreads();
    }
}

// ---------------------------------------------------------------------------
// neighbor gather + LN (scrambled unfold reshape, see R0 derivation)
// ---------------------------------------------------------------------------
__global__ __launch_bounds__(96) void gather_ln_k(const float* __restrict__ t1,
                                                  const float* __restrict__ t2,
                                                  const float* __restrict__ g,
                                                  const float* __restrict__ bb,
                                                  float* __restrict__ kv) {
    const int b = blockIdx.x / 196, l = blockIdx.x % 196;
    const int i1 = l / 14, j1 = l % 14;
    __shared__ float s1[16 * 97];
    __shared__ float s2[9 * 97];
    __shared__ float red[2][3];
    const int t = threadIdx.x, warp = t >> 5, lane = t & 31;

    for (int p = 0; p < 16; ++p) {
        int ki = p >> 2, kj = p & 3;
        s1[p * 97 + t] = t1[((b * 56 + i1 * 4 + ki) * 56 + j1 * 4 + kj) * 96 + t];
    }
    for (int p = 0; p < 9; ++p) {
        int ki = p / 3, kj = p % 3;
        int rr = i1 * 3 + ki - 5, cc = j1 * 3 + kj - 5;
        float v = 0.f;
        if (rr >= 0 && rr < 32 && cc >= 0 && cc < 32)
            v = t2[((b * 32 + rr) * 32 + cc) * 96 + t];
        s2[p * 97 + t] = v;
    }
    __syncthreads();
    const float gg = g[t], bv = bb[t];

    for (int k = 0; k < 25; ++k) {
        float v;
        if (k < 16) {
            int F = k * 96 + t;
            int c = F >> 4, rem = F & 15;
            v = s1[rem * 97 + c];
        } else {
            int F = (k - 16) * 96 + t;
            int c = F / 9, rem = F % 9;
            v = s2[rem * 97 + c];
        }
        float s = v, s2s = v * v;
#pragma unroll
        for (int o = 16; o > 0; o >>= 1) {
            s += __shfl_xor_sync(0xffffffffu, s, o);
            s2s += __shfl_xor_sync(0xffffffffu, s2s, o);
        }
        if (lane == 0) { red[0][warp] = s; red[1][warp] = s2s; }
        __syncthreads();
        float S = red[0][0] + red[0][1] + red[0][2];
        float S2 = red[1][0] + red[1][1] + red[1][2];
        float mean = S * (1.f / 96.f);
        float var = fmaf(-mean, mean, S2 * (1.f / 96.f));
        kv[(blockIdx.x * 25 + k) * 96 + t] = (v - mean) * rsqrtf(var + 1e-5f) * gg + bv;
        __syncthreads();
    }
}

// ---------------------------------------------------------------------------
// cross attention: 1 query vs 25 keys, d=96, scale 1/sqrt(96)
// ---------------------------------------------------------------------------
__global__ __launch_bounds__(96) void cross_attn_k(const float* __restrict__ q,
                                                   const float* __restrict__ kbuf,
                                                   const float* __restrict__ vbuf,
                                                   float* __restrict__ o) {
    const int rl = blockIdx.x;
    __shared__ float sk[25][97], sv[25][97], sq[96], ss[25];
    const int t = threadIdx.x;
    sq[t] = q[rl * 96 + t];
    for (int k = 0; k < 25; ++k) {
        sk[k][t] = kbuf[(rl * 25 + k) * 96 + t];
        sv[k][t] = vbuf[(rl * 25 + k) * 96 + t];
    }
    __syncthreads();
    if (t < 25) {
        float s = 0.f;
        for (int c = 0; c < 96; ++c) s = fmaf(sq[c], sk[t][c], s);
        ss[t] = s * 0.10206207261596575f;  // 1/sqrt(96)
    }
    __syncthreads();
    float m = -1e30f;
#pragma unroll
    for (int k = 0; k < 25; ++k) m = fmaxf(m, ss[k]);
    float Z = 0.f, acc = 0.f;
#pragma unroll
    for (int k = 0; k < 25; ++k) {
        float e = __expf(ss[k] - m);
        Z += e;
        acc = fmaf(e, sv[k][t], acc);
    }
    o[rl * 96 + t] = acc / Z;
}

// ---------------------------------------------------------------------------
extern "C" void kernel_launch(void* const* d_in, const int* in_sizes, int n_in,
                              void* d_out, int out_size) {
    const float* x       = (const float*)d_in[0];
    const float* pw[3]   = {(const float*)d_in[1], (const float*)d_in[3], (const float*)d_in[5]};
    const float* pb[3]   = {(const float*)d_in[2], (const float*)d_in[4], (const float*)d_in[6]};
    const float* wa_ln_g = (const float*)d_in[7];
    const float* wa_ln_b = (const float*)d_in[8];
    const float* wa_qkv  = (const float*)d_in[9];
    const float* wa_ow   = (const float*)d_in[10];
    const float* wa_ob   = (const float*)d_in[11];
    const float* ff_ln_g = (const float*)d_in[12];
    const float* ff_ln_b = (const float*)d_in[13];
    const float* ff_w1   = (const float*)d_in[14];
    const float* ff_b1   = (const float*)d_in[15];
    const float* ff_w2   = (const float*)d_in[16];
    const float* ff_b2   = (const float*)d_in[17];
    const float* lnn_g   = (const float*)d_in[18];
    const float* lnn_b   = (const float*)d_in[19];
    const float* ca_wq   = (const float*)d_in[20];
    const float* ca_wk   = (const float*)d_in[21];
    const float* ca_wv   = (const float*)d_in[22];
    const float* ca_wo   = (const float*)d_in[23];
    const float* ca_bo   = (const float*)d_in[24];
    const float* fi_ln_g = (const float*)d_in[25];
    const float* fi_ln_b = (const float*)d_in[26];
    const float* fi_w1   = (const float*)d_in[27];
    const float* fi_b1   = (const float*)d_in[28];
    const float* fi_w2   = (const float*)d_in[29];
    const float* fi_b2   = (const float*)d_in[30];
    float* out = (float*)d_out;

    float *t0, *t1, *t2, *qkv, *ob, *kv, *kk, *vv, *qq, *co;
    cudaGetSymbolAddress((void**)&t0, g_t0);
    cudaGetSymbolAddress((void**)&t1, g_t1);
    cudaGetSymbolAddress((void**)&t2, g_t2);
    cudaGetSymbolAddress((void**)&qkv, g_qkv);
    cudaGetSymbolAddress((void**)&ob, g_ob);
    cudaGetSymbolAddress((void**)&kv, g_kv);
    cudaGetSymbolAddress((void**)&kk, g_k);
    cudaGetSymbolAddress((void**)&vv, g_v);
    cudaGetSymbolAddress((void**)&qq, g_q);
    cudaGetSymbolAddress((void**)&co, g_co);

    // patch merges (tensor core)
    patch_tc<16, 768, 14><<<ROWS0 / 64, 128>>>(x, pw[0], pb[0], t0);
    patch_tc<4, 48, 56><<<ROWS1 / 64, 128>>>(x, pw[1], pb[1], t1);
    patch_tc<7, 147, 32><<<ROWS2 / 64, 128>>>(x, pw[2], pb[2], t2);

    const int rows[3] = {ROWS0, ROWS1, ROWS2};
    float* tb[3] = {t0, t1, t2};
    for (int i = 0; i < 3; ++i) {
        const int R = rows[i];
        float* t = tb[i];
        // qkv = LN(t) @ Wqkv
        gemm_tc<true, false, 0><<<dim3(R / 64, 3), 128>>>(
            t, wa_qkv + i * 96 * 288, nullptr, wa_ln_g + i * 96, wa_ln_b + i * 96, nullptr, qkv, 288);
        if (i == 0)      win_attn_k<7><<<64 * 2 * 2, 128>>>(qkv, ob, 14, 2);
        else if (i == 1) win_attn_k<4><<<64 * 14 * 14, 128>>>(qkv, ob, 56, 14);
        else             win_attn_k<4><<<64 * 8 * 8, 128>>>(qkv, ob, 32, 8);
        // t += attn_out @ Wo + bo
        gemm_tc<false, false, 1><<<dim3(R / 64, 1), 128>>>(
            ob, wa_ow + i * 9216, wa_ob + i * 96, nullptr, nullptr, nullptr, t, 96);
        // h = gelu(LN(t) @ W1 + b1)
        gemm_tc<true, true, 0><<<dim3(R / 64, 1), 128>>>(
            t, ff_w1 + i * 9216, ff_b1 + i * 96, ff_ln_g + i * 96, ff_ln_b + i * 96, nullptr, ob, 96);
        // t += h @ W2 + b2
        gemm_tc<false, false, 1><<<dim3(R / 64, 1), 128>>>(
            ob, ff_w2 + i * 9216, ff_b2 + i * 96, nullptr, nullptr, nullptr, t, 96);
    }

    // neighbor gather + LN -> kv
    gather_ln_k<<<64 * 196, 96>>>(t1, t2, lnn_g, lnn_b, kv);
    // k / v projections (inputs already LN'd)
    gemm_tc<false, false, 0><<<dim3(KVROWS / 64, 1), 128>>>(kv, ca_wk, nullptr, nullptr, nullptr, nullptr, kk, 96);
    gemm_tc<false, false, 0><<<dim3(KVROWS / 64, 1), 128>>>(kv, ca_wv, nullptr, nullptr, nullptr, nullptr, vv, 96);
    // q = LN(x1) @ Wq
    gemm_tc<true, false, 0><<<dim3(ROWS0 / 64, 1), 128>>>(t0, ca_wq, nullptr, lnn_g, lnn_b, nullptr, qq, 96);
    // cross attention
    cross_attn_k<<<12544, 96>>>(qq, kk, vv, co);
    // out = x1 + o @ Wo + bo
    gemm_tc<false, false, 2><<<dim3(ROWS0 / 64, 1), 128>>>(co, ca_wo, ca_bo, nullptr, nullptr, t0, out, 96);
    // out += gelu(LN(out) @ w1 + b1) @ w2 + b2
    gemm_tc<true, true, 0><<<dim3(ROWS0 / 64, 1), 128>>>(out, fi_w1, fi_b1, fi_ln_g, fi_ln_b, nullptr, co, 96);
    gemm_tc<false, false, 1><<<dim3(ROWS0 / 64, 1), 128>>>(co, fi_w2, fi_b2, nullptr, nullptr, nullptr, out, 96);
}

// round 3
// speedup vs baseline: 1.6865x; 1.1719x over previous
#include <cuda_runtime.h>
#include <math.h>

// ---------------------------------------------------------------------------
// MultiScaleCrossAttn — tf32 tensor-core GEMMs (128x96 tiles, smem-staged B)
// ---------------------------------------------------------------------------

#define ROWS0 12544      // 64*14*14
#define ROWS1 200704     // 64*56*56
#define ROWS2 65536      // 64*32*32
#define KVROWS 313600    // 64*196*25

// scratch (device globals; no allocation allowed)
__device__ float g_t0[ROWS0 * 96];
__device__ float g_t1[ROWS1 * 96];
__device__ float g_t2[ROWS2 * 96];
__device__ float g_qkv[ROWS1 * 288];
__device__ float g_ob[ROWS1 * 96];
__device__ float g_kv[KVROWS * 96];
__device__ float g_k[KVROWS * 96];
__device__ float g_v[KVROWS * 96];
__device__ float g_q[ROWS0 * 96];
__device__ float g_co[ROWS0 * 96];

static constexpr int AS_WORDS = 12 * 8 * 32 * 4;  // 12288
static constexpr int BS_WORDS = 12 * 6 * 32 * 4;  // 9216
static constexpr int GSMEM = (AS_WORDS + BS_WORDS) * 4;  // 86016 B

__device__ __forceinline__ unsigned f2tf(float f) {
    unsigned u;
    asm("cvt.rna.tf32.f32 %0, %1;" : "=r"(u) : "f"(f));
    return u;
}

__device__ __forceinline__ void mma8(float c[4], uint4 a, unsigned b0, unsigned b1) {
    asm volatile(
        "mma.sync.aligned.m16n8k8.row.col.f32.tf32.tf32.f32 "
        "{%0,%1,%2,%3}, {%4,%5,%6,%7}, {%8,%9}, {%0,%1,%2,%3};\n"
        : "+f"(c[0]), "+f"(c[1]), "+f"(c[2]), "+f"(c[3])
        : "r"(a.x), "r"(a.y), "r"(a.z), "r"(a.w), "r"(b0), "r"(b1));
}

__device__ __forceinline__ float gelu_f(float v) {
    return 0.5f * v * (1.f + erff(v * 0.70710678118654752f));
}

// ---------------------------------------------------------------------------
// K=96 row-GEMM. 256 thr, tile 128 rows x 96 cols; blockIdx.y = 96-col chunk.
// A (+optional LN) -> tf32 frag smem (uint4-packed); B staged to frag smem.
// Warp w: mtiles {2*(w&3), 2*(w&3)+1}, ntiles {6*(w>>2)..+5}.
// ---------------------------------------------------------------------------
template <bool LNF, bool GELU, int EPI>
__global__ __launch_bounds__(256, 2) void gemm_tc(const float* __restrict__ A,
                                                  const float* __restrict__ W,
                                                  const float* __restrict__ bias,
                                                  const float* __restrict__ lng,
                                                  const float* __restrict__ lnb,
                                                  const float* __restrict__ res,
                                                  float* __restrict__ out, int ldw) {
    extern __shared__ unsigned dynsm[];
    unsigned* As = dynsm;
    unsigned* Bs = dynsm + AS_WORDS;
    const int tid = threadIdx.x, lane = tid & 31, warp = tid >> 5;
    const int row0 = blockIdx.x * 128, ncol0 = blockIdx.y * 96;

    // ---- stage B 96x96 slice in frag order: Bs[((kt*6+jp)*32+ln)*4+c] ----
    for (int idx = tid; idx < BS_WORDS; idx += 256) {
        int kt = idx / 768;
        int r = idx - kt * 768;
        int jp = r >> 7;
        int r2 = r & 127;
        int ln = r2 >> 2, c = r2 & 3;
        int k = kt * 8 + (ln & 3) + ((c & 1) << 2);
        int n = ((jp << 1) + (c >> 1)) * 8 + (ln >> 2);
        Bs[idx] = f2tf(__ldg(&W[k * ldw + ncol0 + n]));
    }

    // ---- stage A (+LN): 2 threads per row ----
    {
        const int row = tid >> 1, sub = tid & 1;
        const float* ap = A + (size_t)(row0 + row) * 96 + sub * 48;
        float4 vals[12];
#pragma unroll
        for (int j = 0; j < 12; ++j) vals[j] = __ldg((const float4*)(ap + j * 4));
        float mean = 0.f, rstd = 0.f;
        if (LNF) {
            float s = 0.f, s2 = 0.f;
#pragma unroll
            for (int j = 0; j < 12; ++j) {
                float4 v = vals[j];
                s += v.x + v.y + v.z + v.w;
                s2 += v.x * v.x + v.y * v.y + v.z * v.z + v.w * v.w;
            }
            s += __shfl_xor_sync(0xffffffffu, s, 1);
            s2 += __shfl_xor_sync(0xffffffffu, s2, 1);
            mean = s * (1.f / 96.f);
            float var = fmaf(-mean, mean, s2 * (1.f / 96.f));
            rstd = rsqrtf(var + 1e-5f);
        }
        const int mt = row >> 4;
        const int lbase = (row & 7) << 2;
        const int ibit = (row >> 3) & 1;
#pragma unroll
        for (int j = 0; j < 12; ++j) {
            int k0 = sub * 48 + j * 4;
            float4 v = vals[j];
            if (LNF) {
                float4 g = __ldg((const float4*)(lng + k0));
                float4 bb = __ldg((const float4*)(lnb + k0));
                v.x = (v.x - mean) * rstd * g.x + bb.x;
                v.y = (v.y - mean) * rstd * g.y + bb.y;
                v.z = (v.z - mean) * rstd * g.z + bb.z;
                v.w = (v.w - mean) * rstd * g.w + bb.w;
            }
            int kt = k0 >> 3;
            int i = (((k0 >> 2) & 1) << 1) | ibit;
            unsigned base = (((kt * 8 + mt) * 32) + lbase) * 4 + i;
            As[base] = f2tf(v.x);
            As[base + 4] = f2tf(v.y);
            As[base + 8] = f2tf(v.z);
            As[base + 12] = f2tf(v.w);
        }
    }
    __syncthreads();

    // ---- mainloop ----
    const int mg = warp & 3, nh = warp >> 2;
    float acc[2][6][4];
#pragma unroll
    for (int m = 0; m < 2; ++m)
#pragma unroll
        for (int j = 0; j < 6; ++j)
#pragma unroll
            for (int i = 0; i < 4; ++i) acc[m][j][i] = 0.f;

    const uint4* As4 = (const uint4*)As;
    const uint4* Bs4 = (const uint4*)Bs;
#pragma unroll
    for (int kt = 0; kt < 12; ++kt) {
        uint4 a0 = As4[(kt * 8 + mg * 2) * 32 + lane];
        uint4 a1 = As4[(kt * 8 + mg * 2 + 1) * 32 + lane];
        uint4 b0 = Bs4[(kt * 6 + nh * 3) * 32 + lane];
        uint4 b1 = Bs4[(kt * 6 + nh * 3 + 1) * 32 + lane];
        uint4 b2 = Bs4[(kt * 6 + nh * 3 + 2) * 32 + lane];
        mma8(acc[0][0], a0, b0.x, b0.y); mma8(acc[0][1], a0, b0.z, b0.w);
        mma8(acc[0][2], a0, b1.x, b1.y); mma8(acc[0][3], a0, b1.z, b1.w);
        mma8(acc[0][4], a0, b2.x, b2.y); mma8(acc[0][5], a0, b2.z, b2.w);
        mma8(acc[1][0], a1, b0.x, b0.y); mma8(acc[1][1], a1, b0.z, b0.w);
        mma8(acc[1][2], a1, b1.x, b1.y); mma8(acc[1][3], a1, b1.z, b1.w);
        mma8(acc[1][4], a1, b2.x, b2.y); mma8(acc[1][5], a1, b2.z, b2.w);
    }

    // ---- epilogue (float2 stores) ----
    const int gid = lane >> 2, tig = lane & 3;
#pragma unroll
    for (int m = 0; m < 2; ++m) {
        int rr = row0 + (mg * 2 + m) * 16 + gid;
#pragma unroll
        for (int j = 0; j < 6; ++j) {
            int nc = ncol0 + (nh * 6 + j) * 8 + tig * 2;
            float bx = 0.f, by = 0.f;
            if (bias) {
                float2 bv = *(const float2*)&bias[nc];
                bx = bv.x; by = bv.y;
            }
            float x0 = acc[m][j][0] + bx, x1 = acc[m][j][1] + by;
            float x2 = acc[m][j][2] + bx, x3 = acc[m][j][3] + by;
            if (GELU) { x0 = gelu_f(x0); x1 = gelu_f(x1); x2 = gelu_f(x2); x3 = gelu_f(x3); }
            float* p0 = &out[(size_t)rr * ldw + nc];
            float* p1 = &out[(size_t)(rr + 8) * ldw + nc];
            if constexpr (EPI == 0) {
                *(float2*)p0 = make_float2(x0, x1);
                *(float2*)p1 = make_float2(x2, x3);
            } else if constexpr (EPI == 1) {
                float2 o0 = *(float2*)p0, o1 = *(float2*)p1;
                *(float2*)p0 = make_float2(o0.x + x0, o0.y + x1);
                *(float2*)p1 = make_float2(o1.x + x2, o1.y + x3);
            } else {
                float2 r0 = *(const float2*)&res[(size_t)rr * 96 + nc];
                float2 r1 = *(const float2*)&res[(size_t)(rr + 8) * 96 + nc];
                *(float2*)p0 = make_float2(r0.x + x0, r0.y + x1);
                *(float2*)p1 = make_float2(r1.x + x2, r1.y + x3);
            }
        }
    }
}

// ---------------------------------------------------------------------------
// patch merge on the same engine: gather unfold features, K chunked by 96
// ---------------------------------------------------------------------------
template <int DF, int KTOT, int WOUT>
__global__ __launch_bounds__(256, 2) void patch_tc(const float* __restrict__ x,
                                                   const float* __restrict__ w,
                                                   const float* __restrict__ bias,
                                                   float* __restrict__ out) {
    constexpr int KPAD = (KTOT + 7) & ~7;
    extern __shared__ unsigned dynsm[];
    unsigned* As = dynsm;
    unsigned* Bs = dynsm + AS_WORDS;
    const int tid = threadIdx.x, lane = tid & 31, warp = tid >> 5;
    const int row0 = blockIdx.x * 128;
    const int T = WOUT * WOUT;
    const int mg = warp & 3, nh = warp >> 2;

    float acc[2][6][4];
#pragma unroll
    for (int m = 0; m < 2; ++m)
#pragma unroll
        for (int j = 0; j < 6; ++j)
#pragma unroll
            for (int i = 0; i < 4; ++i) acc[m][j][i] = 0.f;

    const uint4* As4 = (const uint4*)As;
    const uint4* Bs4 = (const uint4*)Bs;

    for (int kc = 0; kc < KPAD; kc += 96) {
        const int cl = (KPAD - kc) < 96 ? (KPAD - kc) : 96;
        const int nkt = cl >> 3;

        for (int idx = tid; idx < nkt * 768; idx += 256) {
            int kt = idx / 768;
            int r = idx - kt * 768;
            int jp = r >> 7;
            int r2 = r & 127;
            int ln = r2 >> 2, c = r2 & 3;
            int k = kc + kt * 8 + (ln & 3) + ((c & 1) << 2);
            int n = ((jp << 1) + (c >> 1)) * 8 + (ln >> 2);
            Bs[idx] = (k < KTOT) ? f2tf(__ldg(&w[k * 96 + n])) : 0u;
        }
        {
            const int row = tid >> 1, sub = tid & 1;
            const int tok = row0 + row;
            const int b = tok / T, hw = tok - b * T;
            const int h = hw / WOUT, ww = hw - h * WOUT;
            const int mt = row >> 4;
            const int lbase = (row & 7) << 2;
            const int ibit = (row >> 3) & 1;
#pragma unroll
            for (int j = 0; j < 12; ++j) {
                int k0 = sub * 48 + j * 4;
                if (k0 >= cl) break;
                int kt = k0 >> 3;
                int i = (((k0 >> 2) & 1) << 1) | ibit;
                unsigned base = (((kt * 8 + mt) * 32) + lbase) * 4 + i;
#pragma unroll
                for (int e = 0; e < 4; ++e) {
                    int f = kc + k0 + e;
                    float v = 0.f;
                    if (f < KTOT) {
                        int c2 = f / (DF * DF), rem = f - c2 * DF * DF;
                        int ki = rem / DF, kj = rem - ki * DF;
                        v = __ldg(&x[((b * 3 + c2) * 224 + h * DF + ki) * 224 + ww * DF + kj]);
                    }
                    As[base + e * 4] = f2tf(v);
                }
            }
        }
        __syncthreads();

        for (int kt = 0; kt < nkt; ++kt) {
            uint4 a0 = As4[(kt * 8 + mg * 2) * 32 + lane];
            uint4 a1 = As4[(kt * 8 + mg * 2 + 1) * 32 + lane];
            uint4 b0 = Bs4[(kt * 6 + nh * 3) * 32 + lane];
            uint4 b1 = Bs4[(kt * 6 + nh * 3 + 1) * 32 + lane];
            uint4 b2 = Bs4[(kt * 6 + nh * 3 + 2) * 32 + lane];
            mma8(acc[0][0], a0, b0.x, b0.y); mma8(acc[0][1], a0, b0.z, b0.w);
            mma8(acc[0][2], a0, b1.x, b1.y); mma8(acc[0][3], a0, b1.z, b1.w);
            mma8(acc[0][4], a0, b2.x, b2.y); mma8(acc[0][5], a0, b2.z, b2.w);
            mma8(acc[1][0], a1, b0.x, b0.y); mma8(acc[1][1], a1, b0.z, b0.w);
            mma8(acc[1][2], a1, b1.x, b1.y); mma8(acc[1][3], a1, b1.z, b1.w);
            mma8(acc[1][4], a1, b2.x, b2.y); mma8(acc[1][5], a1, b2.z, b2.w);
        }
        __syncthreads();
    }

    const int gid = lane >> 2, tig = lane & 3;
#pragma unroll
    for (int m = 0; m < 2; ++m) {
        int rr = row0 + (mg * 2 + m) * 16 + gid;
#pragma unroll
        for (int j = 0; j < 6; ++j) {
            int nc = (nh * 6 + j) * 8 + tig * 2;
            float2 bv = *(const float2*)&bias[nc];
            *(float2*)&out[(size_t)rr * 96 + nc] =
                make_float2(acc[m][j][0] + bv.x, acc[m][j][1] + bv.y);
            *(float2*)&out[(size_t)(rr + 8) * 96 + nc] =
                make_float2(acc[m][j][2] + bv.x, acc[m][j][3] + bv.y);
        }
    }
}

// ---------------------------------------------------------------------------
// window attention: one block per (batch, window), 3 heads serial, hd=32
// ---------------------------------------------------------------------------
template <int WS>
__global__ __launch_bounds__(128) void win_attn_k(const float* __restrict__ qkv,
                                                  float* __restrict__ o,
                                                  int Wout, int nw) {
    constexpr int NT = WS * WS;
    __shared__ float sq[NT][33], sk[NT][33], sv[NT][33];
    __shared__ float sS[NT * NT];
    const int b = blockIdx.x / (nw * nw);
    const int win = blockIdx.x % (nw * nw);
    const int wr = win / nw, wc = win % nw;
    const int t = threadIdx.x;
    const int T = Wout * Wout;
    const float scale = 0.17677669529663687f;

    for (int head = 0; head < 3; ++head) {
        for (int idx = t; idx < NT * 32; idx += 128) {
            int p = idx >> 5, c = idx & 31;
            int wi = p / WS, wj = p % WS;
            int r = b * T + (wr * WS + wi) * Wout + wc * WS + wj;
            const float* base = qkv + (size_t)r * 288 + head * 32 + c;
            sq[p][c] = base[0];
            sk[p][c] = base[96];
            sv[p][c] = base[192];
        }
        __syncthreads();
        for (int idx = t; idx < NT * NT; idx += 128) {
            int i = idx / NT, j = idx % NT;
            float s = 0.f;
#pragma unroll
            for (int c = 0; c < 32; ++c) s = fmaf(sq[i][c], sk[j][c], s);
            sS[idx] = s * scale;
        }
        __syncthreads();
        if (t < NT) {
            float m = -1e30f;
            for (int j = 0; j < NT; ++j) m = fmaxf(m, sS[t * NT + j]);
            float Z = 0.f;
            for (int j = 0; j < NT; ++j) {
                float e = __expf(sS[t * NT + j] - m);
                sS[t * NT + j] = e;
                Z += e;
            }
            float inv = 1.f / Z;
            for (int j = 0; j < NT; ++j) sS[t * NT + j] *= inv;
        }
        __syncthreads();
        for (int idx = t; idx < NT * 32; idx += 128) {
            int i = idx >> 5, c = idx & 31;
            float acc = 0.f;
            for (int j = 0; j < NT; ++j) acc = fmaf(sS[i * NT + j], sv[j][c], acc);
            int wi = i / WS, wj = i % WS;
            int r = b * T + (wr * WS + wi) * Wout + wc * WS + wj;
            o[(size_t)r * 96 + head * 32 + c] = acc;
        }
        __syncthreads();
    }
}

// ---------------------------------------------------------------------------
// neighbor gather + LN (scrambled unfold reshape)
// ---------------------------------------------------------------------------
__global__ __launch_bounds__(96) void gather_ln_k(const float* __restrict__ t1,
                                                  const float* __restrict__ t2,
                                                  const float* __restrict__ g,
                                                  const float* __restrict__ bb,
                                                  float* __restrict__ kv) {
    const int b = blockIdx.x / 196, l = blockIdx.x % 196;
    const int i1 = l / 14, j1 = l % 14;
    __shared__ float s1[16 * 97];
    __shared__ float s2[9 * 97];
    __shared__ float red[2][3];
    const int t = threadIdx.x, warp = t >> 5, lane = t & 31;

    for (int p = 0; p < 16; ++p) {
        int ki = p >> 2, kj = p & 3;
        s1[p * 97 + t] = t1[(size_t)((b * 56 + i1 * 4 + ki) * 56 + j1 * 4 + kj) * 96 + t];
    }
    for (int p = 0; p < 9; ++p) {
        int ki = p / 3, kj = p % 3;
        int rr = i1 * 3 + ki - 5, cc = j1 * 3 + kj - 5;
        float v = 0.f;
        if (rr >= 0 && rr < 32 && cc >= 0 && cc < 32)
            v = t2[(size_t)((b * 32 + rr) * 32 + cc) * 96 + t];
        s2[p * 97 + t] = v;
    }
    __syncthreads();
    const float gg = g[t], bv = bb[t];

    for (int k = 0; k < 25; ++k) {
        float v;
        if (k < 16) {
            int F = k * 96 + t;
            int c = F >> 4, rem = F & 15;
            v = s1[rem * 97 + c];
        } else {
            int F = (k - 16) * 96 + t;
            int c = F / 9, rem = F % 9;
            v = s2[rem * 97 + c];
        }
        float s = v, s2s = v * v;
#pragma unroll
        for (int o = 16; o > 0; o >>= 1) {
            s += __shfl_xor_sync(0xffffffffu, s, o);
            s2s += __shfl_xor_sync(0xffffffffu, s2s, o);
        }
        if (lane == 0) { red[0][warp] = s; red[1][warp] = s2s; }
        __syncthreads();
        float S = red[0][0] + red[0][1] + red[0][2];
        float S2 = red[1][0] + red[1][1] + red[1][2];
        float mean = S * (1.f / 96.f);
        float var = fmaf(-mean, mean, S2 * (1.f / 96.f));
        kv[((size_t)blockIdx.x * 25 + k) * 96 + t] = (v - mean) * rsqrtf(var + 1e-5f) * gg + bv;
        __syncthreads();
    }
}

// ---------------------------------------------------------------------------
// cross attention: 1 query vs 25 keys, d=96
// ---------------------------------------------------------------------------
__global__ __launch_bounds__(96) void cross_attn_k(const float* __restrict__ q,
                                                   const float* __restrict__ kbuf,
                                                   const float* __restrict__ vbuf,
                                                   float* __restrict__ o) {
    const int rl = blockIdx.x;
    __shared__ float sk[25][97], sv[25][97], sq[96], ss[25];
    const int t = threadIdx.x;
    sq[t] = q[(size_t)rl * 96 + t];
    for (int k = 0; k < 25; ++k) {
        sk[k][t] = kbuf[((size_t)rl * 25 + k) * 96 + t];
        sv[k][t] = vbuf[((size_t)rl * 25 + k) * 96 + t];
    }
    __syncthreads();
    if (t < 25) {
        float s = 0.f;
        for (int c = 0; c < 96; ++c) s = fmaf(sq[c], sk[t][c], s);
        ss[t] = s * 0.10206207261596575f;
    }
    __syncthreads();
    float m = -1e30f;
#pragma unroll
    for (int k = 0; k < 25; ++k) m = fmaxf(m, ss[k]);
    float Z = 0.f, acc = 0.f;
#pragma unroll
    for (int k = 0; k < 25; ++k) {
        float e = __expf(ss[k] - m);
        Z += e;
        acc = fmaf(e, sv[k][t], acc);
    }
    o[(size_t)rl * 96 + t] = acc / Z;
}

// ---------------------------------------------------------------------------
extern "C" void kernel_launch(void* const* d_in, const int* in_sizes, int n_in,
                              void* d_out, int out_size) {
    const float* x       = (const float*)d_in[0];
    const float* pw[3]   = {(const float*)d_in[1], (const float*)d_in[3], (const float*)d_in[5]};
    const float* pb[3]   = {(const float*)d_in[2], (const float*)d_in[4], (const float*)d_in[6]};
    const float* wa_ln_g = (const float*)d_in[7];
    const float* wa_ln_b = (const float*)d_in[8];
    const float* wa_qkv  = (const float*)d_in[9];
    const float* wa_ow   = (const float*)d_in[10];
    const float* wa_ob   = (const float*)d_in[11];
    const float* ff_ln_g = (const float*)d_in[12];
    const float* ff_ln_b = (const float*)d_in[13];
    const float* ff_w1   = (const float*)d_in[14];
    const float* ff_b1   = (const float*)d_in[15];
    const float* ff_w2   = (const float*)d_in[16];
    const float* ff_b2   = (const float*)d_in[17];
    const float* lnn_g   = (const float*)d_in[18];
    const float* lnn_b   = (const float*)d_in[19];
    const float* ca_wq   = (const float*)d_in[20];
    const float* ca_wk   = (const float*)d_in[21];
    const float* ca_wv   = (const float*)d_in[22];
    const float* ca_wo   = (const float*)d_in[23];
    const float* ca_bo   = (const float*)d_in[24];
    const float* fi_ln_g = (const float*)d_in[25];
    const float* fi_ln_b = (const float*)d_in[26];
    const float* fi_w1   = (const float*)d_in[27];
    const float* fi_b1   = (const float*)d_in[28];
    const float* fi_w2   = (const float*)d_in[29];
    const float* fi_b2   = (const float*)d_in[30];
    float* out = (float*)d_out;

    float *t0, *t1, *t2, *qkv, *ob, *kv, *kk, *vv, *qq, *co;
    cudaGetSymbolAddress((void**)&t0, g_t0);
    cudaGetSymbolAddress((void**)&t1, g_t1);
    cudaGetSymbolAddress((void**)&t2, g_t2);
    cudaGetSymbolAddress((void**)&qkv, g_qkv);
    cudaGetSymbolAddress((void**)&ob, g_ob);
    cudaGetSymbolAddress((void**)&kv, g_kv);
    cudaGetSymbolAddress((void**)&kk, g_k);
    cudaGetSymbolAddress((void**)&vv, g_v);
    cudaGetSymbolAddress((void**)&qq, g_q);
    cudaGetSymbolAddress((void**)&co, g_co);

    // opt-in dynamic smem (idempotent; host-side, capture-safe)
    cudaFuncSetAttribute(gemm_tc<true, false, 0>, cudaFuncAttributeMaxDynamicSharedMemorySize, GSMEM);
    cudaFuncSetAttribute(gemm_tc<false, false, 0>, cudaFuncAttributeMaxDynamicSharedMemorySize, GSMEM);
    cudaFuncSetAttribute(gemm_tc<false, false, 1>, cudaFuncAttributeMaxDynamicSharedMemorySize, GSMEM);
    cudaFuncSetAttribute(gemm_tc<false, false, 2>, cudaFuncAttributeMaxDynamicSharedMemorySize, GSMEM);
    cudaFuncSetAttribute(gemm_tc<true, true, 0>, cudaFuncAttributeMaxDynamicSharedMemorySize, GSMEM);
    cudaFuncSetAttribute(patch_tc<16, 768, 14>, cudaFuncAttributeMaxDynamicSharedMemorySize, GSMEM);
    cudaFuncSetAttribute(patch_tc<4, 48, 56>, cudaFuncAttributeMaxDynamicSharedMemorySize, GSMEM);
    cudaFuncSetAttribute(patch_tc<7, 147, 32>, cudaFuncAttributeMaxDynamicSharedMemorySize, GSMEM);

    // patch merges
    patch_tc<16, 768, 14><<<ROWS0 / 128, 256, GSMEM>>>(x, pw[0], pb[0], t0);
    patch_tc<4, 48, 56><<<ROWS1 / 128, 256, GSMEM>>>(x, pw[1], pb[1], t1);
    patch_tc<7, 147, 32><<<ROWS2 / 128, 256, GSMEM>>>(x, pw[2], pb[2], t2);

    const int rows[3] = {ROWS0, ROWS1, ROWS2};
    float* tb[3] = {t0, t1, t2};
    for (int i = 0; i < 3; ++i) {
        const int R = rows[i];
        float* t = tb[i];
        gemm_tc<true, false, 0><<<dim3(R / 128, 3), 256, GSMEM>>>(
            t, wa_qkv + i * 96 * 288, nullptr, wa_ln_g + i * 96, wa_ln_b + i * 96, nullptr, qkv, 288);
        if (i == 0)      win_attn_k<7><<<64 * 2 * 2, 128>>>(qkv, ob, 14, 2);
        else if (i == 1) win_attn_k<4><<<64 * 14 * 14, 128>>>(qkv, ob, 56, 14);
        else             win_attn_k<4><<<64 * 8 * 8, 128>>>(qkv, ob, 32, 8);
        gemm_tc<false, false, 1><<<dim3(R / 128, 1), 256, GSMEM>>>(
            ob, wa_ow + i * 9216, wa_ob + i * 96, nullptr, nullptr, nullptr, t, 96);
        gemm_tc<true, true, 0><<<dim3(R / 128, 1), 256, GSMEM>>>(
            t, ff_w1 + i * 9216, ff_b1 + i * 96, ff_ln_g + i * 96, ff_ln_b + i * 96, nullptr, ob, 96);
        gemm_tc<false, false, 1><<<dim3(R / 128, 1), 256, GSMEM>>>(
            ob, ff_w2 + i * 9216, ff_b2 + i * 96, nullptr, nullptr, nullptr, t, 96);
    }

    gather_ln_k<<<64 * 196, 96>>>(t1, t2, lnn_g, lnn_b, kv);
    gemm_tc<false, false, 0><<<dim3(KVROWS / 128, 1), 256, GSMEM>>>(kv, ca_wk, nullptr, nullptr, nullptr, nullptr, kk, 96);
    gemm_tc<false, false, 0><<<dim3(KVROWS / 128, 1), 256, GSMEM>>>(kv, ca_wv, nullptr, nullptr, nullptr, nullptr, vv, 96);
    gemm_tc<true, false, 0><<<dim3(ROWS0 / 128, 1), 256, GSMEM>>>(t0, ca_wq, nullptr, lnn_g, lnn_b, nullptr, qq, 96);
    cross_attn_k<<<12544, 96>>>(qq, kk, vv, co);
    gemm_tc<false, false, 2><<<dim3(ROWS0 / 128, 1), 256, GSMEM>>>(co, ca_wo, ca_bo, nullptr, nullptr, t0, out, 96);
    gemm_tc<true, true, 0><<<dim3(ROWS0 / 128, 1), 256, GSMEM>>>(out, fi_w1, fi_b1, fi_ln_g, fi_ln_b, nullptr, co, 96);
    gemm_tc<false, false, 1><<<dim3(ROWS0 / 128, 1), 256, GSMEM>>>(co, fi_w2, fi_b2, nullptr, nullptr, nullptr, out, 96);
}

// round 4
// speedup vs baseline: 1.9050x; 1.1296x over previous
#include <cuda_runtime.h>
#include <cuda_fp16.h>
#include <math.h>

// ---------------------------------------------------------------------------
// MultiScaleCrossAttn — fp16 tensor-core GEMMs (m16n8k16, fp32 accum)
// 128x96 tiles, static smem, fused LN/GELU/residual epilogues
// ---------------------------------------------------------------------------

#define ROWS0 12544      // 64*14*14
#define ROWS1 200704     // 64*56*56
#define ROWS2 65536      // 64*32*32
#define KVROWS 313600    // 64*196*25

__device__ float g_t0[ROWS0 * 96];
__device__ float g_t1[ROWS1 * 96];
__device__ float g_t2[ROWS2 * 96];
__device__ float g_qkv[ROWS1 * 288];
__device__ float g_ob[ROWS1 * 96];
__device__ float g_kv[KVROWS * 96];
__device__ float g_k[KVROWS * 96];
__device__ float g_v[KVROWS * 96];
__device__ float g_q[ROWS0 * 96];
__device__ float g_co[ROWS0 * 96];

static constexpr int AS_U4 = 6 * 8 * 32;   // 1536 uint4 = 24KB
static constexpr int BS_U4 = 6 * 6 * 32;   // 1152 uint4 = 18KB

__device__ __forceinline__ unsigned f2h2(float lo, float hi) {
    __half2 h = __floats2half2_rn(lo, hi);
    return *reinterpret_cast<unsigned*>(&h);
}

__device__ __forceinline__ void mma16(float c[4], uint4 a, unsigned b0, unsigned b1) {
    asm volatile(
        "mma.sync.aligned.m16n8k16.row.col.f32.f16.f16.f32 "
        "{%0,%1,%2,%3}, {%4,%5,%6,%7}, {%8,%9}, {%0,%1,%2,%3};\n"
        : "+f"(c[0]), "+f"(c[1]), "+f"(c[2]), "+f"(c[3])
        : "r"(a.x), "r"(a.y), "r"(a.z), "r"(a.w), "r"(b0), "r"(b1));
}

__device__ __forceinline__ float gelu_f(float v) {
    return 0.5f * v * (1.f + erff(v * 0.70710678118654752f));
}

// ---------------------------------------------------------------------------
// K=96 row-GEMM. 256 thr, tile 128 rows x 96 cols; blockIdx.y = 96-col chunk.
// fp16 fragments in smem: As4[(kt*8+mt)*32+lane] = {a0,a1,a2,a3};
// Bs4[(kt*6+jp)*32+lane] = {b0(2jp),b1(2jp),b0(2jp+1),b1(2jp+1)}.
// ---------------------------------------------------------------------------
template <bool LNF, bool GELU, int EPI>
__global__ __launch_bounds__(256, 3) void gemm_tc(const float* __restrict__ A,
                                                  const float* __restrict__ W,
                                                  const float* __restrict__ bias,
                                                  const float* __restrict__ lng,
                                                  const float* __restrict__ lnb,
                                                  const float* __restrict__ res,
                                                  float* __restrict__ out, int ldw) {
    __shared__ uint4 As4[AS_U4];
    __shared__ uint4 Bs4[BS_U4];
    unsigned* As = (unsigned*)As4;
    unsigned* Bs = (unsigned*)Bs4;
    const int tid = threadIdx.x, lane = tid & 31, warp = tid >> 5;
    const int row0 = blockIdx.x * 128, ncol0 = blockIdx.y * 96;

    // ---- stage B (96x96 slice, fp16 frag order) ----
    for (int idx = tid; idx < BS_U4 * 4; idx += 256) {
        int kt = idx / 768;
        int r = idx - kt * 768;
        int jp = r >> 7;
        int r2 = r & 127;
        int ln = r2 >> 2, c = r2 & 3;
        int tig = ln & 3, gid = ln >> 2;
        int n = ncol0 + ((jp << 1) + (c >> 1)) * 8 + gid;
        int k = kt * 16 + 2 * tig + ((c & 1) << 3);
        Bs[idx] = f2h2(__ldg(&W[k * ldw + n]), __ldg(&W[(k + 1) * ldw + n]));
    }

    // ---- stage A (+LN): 2 threads per row, 48 contiguous k each ----
    {
        const int row = tid >> 1, sub = tid & 1;
        const float* ap = A + (size_t)(row0 + row) * 96 + sub * 48;
        float4 vals[12];
#pragma unroll
        for (int j = 0; j < 12; ++j) vals[j] = __ldg((const float4*)(ap + j * 4));
        float mean = 0.f, rstd = 0.f;
        if (LNF) {
            float s = 0.f, s2 = 0.f;
#pragma unroll
            for (int j = 0; j < 12; ++j) {
                float4 v = vals[j];
                s += v.x + v.y + v.z + v.w;
                s2 += v.x * v.x + v.y * v.y + v.z * v.z + v.w * v.w;
            }
            s += __shfl_xor_sync(0xffffffffu, s, 1);
            s2 += __shfl_xor_sync(0xffffffffu, s2, 1);
            mean = s * (1.f / 96.f);
            float var = fmaf(-mean, mean, s2 * (1.f / 96.f));
            rstd = rsqrtf(var + 1e-5f);
        }
        const int mt = row >> 4, r16 = row & 15;
        const int gid = r16 & 7, rowhi = r16 >> 3;
#pragma unroll
        for (int j = 0; j < 12; ++j) {
            int k0 = sub * 48 + j * 4;
            float4 v = vals[j];
            if (LNF) {
                float4 g = __ldg((const float4*)(lng + k0));
                float4 bb = __ldg((const float4*)(lnb + k0));
                v.x = (v.x - mean) * rstd * g.x + bb.x;
                v.y = (v.y - mean) * rstd * g.y + bb.y;
                v.z = (v.z - mean) * rstd * g.z + bb.z;
                v.w = (v.w - mean) * rstd * g.w + bb.w;
            }
            int kt = k0 >> 4, kk = k0 & 15;
            int hi = kk >> 3, tig = (kk & 7) >> 1;
            unsigned base = (((kt * 8 + mt) * 32) + (gid << 2) + tig) * 4;
            As[base + (rowhi | (hi << 1))] = f2h2(v.x, v.y);
            // second pair: k0+2 -> tig+1, same hi/kt
            As[base + 4 + (rowhi | (hi << 1))] = f2h2(v.z, v.w);
        }
    }
    __syncthreads();

    // ---- mainloop: 6 k-steps of 16 ----
    const int mg = warp & 3, nh = warp >> 2;
    float acc[2][6][4];
#pragma unroll
    for (int m = 0; m < 2; ++m)
#pragma unroll
        for (int j = 0; j < 6; ++j)
#pragma unroll
            for (int i = 0; i < 4; ++i) acc[m][j][i] = 0.f;

#pragma unroll
    for (int kt = 0; kt < 6; ++kt) {
        uint4 a0 = As4[(kt * 8 + mg * 2) * 32 + lane];
        uint4 a1 = As4[(kt * 8 + mg * 2 + 1) * 32 + lane];
        uint4 b0 = Bs4[(kt * 6 + nh * 3) * 32 + lane];
        uint4 b1 = Bs4[(kt * 6 + nh * 3 + 1) * 32 + lane];
        uint4 b2 = Bs4[(kt * 6 + nh * 3 + 2) * 32 + lane];
        mma16(acc[0][0], a0, b0.x, b0.y); mma16(acc[0][1], a0, b0.z, b0.w);
        mma16(acc[0][2], a0, b1.x, b1.y); mma16(acc[0][3], a0, b1.z, b1.w);
        mma16(acc[0][4], a0, b2.x, b2.y); mma16(acc[0][5], a0, b2.z, b2.w);
        mma16(acc[1][0], a1, b0.x, b0.y); mma16(acc[1][1], a1, b0.z, b0.w);
        mma16(acc[1][2], a1, b1.x, b1.y); mma16(acc[1][3], a1, b1.z, b1.w);
        mma16(acc[1][4], a1, b2.x, b2.y); mma16(acc[1][5], a1, b2.z, b2.w);
    }

    // ---- epilogue ----
    const int gid = lane >> 2, tig = lane & 3;
#pragma unroll
    for (int m = 0; m < 2; ++m) {
        int rr = row0 + (mg * 2 + m) * 16 + gid;
#pragma unroll
        for (int j = 0; j < 6; ++j) {
            int nc = ncol0 + (nh * 6 + j) * 8 + tig * 2;
            float bx = 0.f, by = 0.f;
            if (bias) {
                float2 bv = *(const float2*)&bias[nc];
                bx = bv.x; by = bv.y;
            }
            float x0 = acc[m][j][0] + bx, x1 = acc[m][j][1] + by;
            float x2 = acc[m][j][2] + bx, x3 = acc[m][j][3] + by;
            if (GELU) { x0 = gelu_f(x0); x1 = gelu_f(x1); x2 = gelu_f(x2); x3 = gelu_f(x3); }
            float* p0 = &out[(size_t)rr * ldw + nc];
            float* p1 = &out[(size_t)(rr + 8) * ldw + nc];
            if constexpr (EPI == 0) {
                *(float2*)p0 = make_float2(x0, x1);
                *(float2*)p1 = make_float2(x2, x3);
            } else if constexpr (EPI == 1) {
                float2 o0 = *(float2*)p0, o1 = *(float2*)p1;
                *(float2*)p0 = make_float2(o0.x + x0, o0.y + x1);
                *(float2*)p1 = make_float2(o1.x + x2, o1.y + x3);
            } else {
                float2 r0 = *(const float2*)&res[(size_t)rr * 96 + nc];
                float2 r1 = *(const float2*)&res[(size_t)(rr + 8) * 96 + nc];
                *(float2*)p0 = make_float2(r0.x + x0, r0.y + x1);
                *(float2*)p1 = make_float2(r1.x + x2, r1.y + x3);
            }
        }
    }
}

// ---------------------------------------------------------------------------
// patch merge on the same fp16 engine: gather unfold features, K chunks of 96
// ---------------------------------------------------------------------------
template <int DF, int KTOT, int WOUT>
__global__ __launch_bounds__(256, 3) void patch_tc(const float* __restrict__ x,
                                                   const float* __restrict__ w,
                                                   const float* __restrict__ bias,
                                                   float* __restrict__ out) {
    constexpr int KPAD = (KTOT + 15) & ~15;
    __shared__ uint4 As4[AS_U4];
    __shared__ uint4 Bs4[BS_U4];
    unsigned* As = (unsigned*)As4;
    unsigned* Bs = (unsigned*)Bs4;
    const int tid = threadIdx.x, lane = tid & 31, warp = tid >> 5;
    const int row0 = blockIdx.x * 128;
    const int T = WOUT * WOUT;
    const int mg = warp & 3, nh = warp >> 2;

    float acc[2][6][4];
#pragma unroll
    for (int m = 0; m < 2; ++m)
#pragma unroll
        for (int j = 0; j < 6; ++j)
#pragma unroll
            for (int i = 0; i < 4; ++i) acc[m][j][i] = 0.f;

    for (int kc = 0; kc < KPAD; kc += 96) {
        const int cl = (KPAD - kc) < 96 ? (KPAD - kc) : 96;
        const int nkt = cl >> 4;

        for (int idx = tid; idx < nkt * 768; idx += 256) {
            int kt = idx / 768;
            int r = idx - kt * 768;
            int jp = r >> 7;
            int r2 = r & 127;
            int ln = r2 >> 2, c = r2 & 3;
            int tig = ln & 3, gid = ln >> 2;
            int n = ((jp << 1) + (c >> 1)) * 8 + gid;
            int k = kc + kt * 16 + 2 * tig + ((c & 1) << 3);
            float lo = (k < KTOT) ? __ldg(&w[k * 96 + n]) : 0.f;
            float hi = (k + 1 < KTOT) ? __ldg(&w[(k + 1) * 96 + n]) : 0.f;
            Bs[idx] = f2h2(lo, hi);
        }
        {
            const int row = tid >> 1, sub = tid & 1;
            const int tok = row0 + row;
            const int b = tok / T, hw = tok - b * T;
            const int h = hw / WOUT, ww = hw - h * WOUT;
            const int mt = row >> 4, r16 = row & 15;
            const int gid = r16 & 7, rowhi = r16 >> 3;
#pragma unroll
            for (int j = 0; j < 12; ++j) {
                int k0 = sub * 48 + j * 4;
                if (k0 >= cl) break;
                float v[4];
#pragma unroll
                for (int e = 0; e < 4; ++e) {
                    int f = kc + k0 + e;
                    float vv = 0.f;
                    if (f < KTOT) {
                        int c2 = f / (DF * DF), rem = f - c2 * DF * DF;
                        int ki = rem / DF, kj = rem - ki * DF;
                        vv = __ldg(&x[((b * 3 + c2) * 224 + h * DF + ki) * 224 + ww * DF + kj]);
                    }
                    v[e] = vv;
                }
                int kt = k0 >> 4, kk = k0 & 15;
                int hi = kk >> 3, tig = (kk & 7) >> 1;
                unsigned base = (((kt * 8 + mt) * 32) + (gid << 2) + tig) * 4;
                As[base + (rowhi | (hi << 1))] = f2h2(v[0], v[1]);
                As[base + 4 + (rowhi | (hi << 1))] = f2h2(v[2], v[3]);
            }
        }
        __syncthreads();

        for (int kt = 0; kt < nkt; ++kt) {
            uint4 a0 = As4[(kt * 8 + mg * 2) * 32 + lane];
            uint4 a1 = As4[(kt * 8 + mg * 2 + 1) * 32 + lane];
            uint4 b0 = Bs4[(kt * 6 + nh * 3) * 32 + lane];
            uint4 b1 = Bs4[(kt * 6 + nh * 3 + 1) * 32 + lane];
            uint4 b2 = Bs4[(kt * 6 + nh * 3 + 2) * 32 + lane];
            mma16(acc[0][0], a0, b0.x, b0.y); mma16(acc[0][1], a0, b0.z, b0.w);
            mma16(acc[0][2], a0, b1.x, b1.y); mma16(acc[0][3], a0, b1.z, b1.w);
            mma16(acc[0][4], a0, b2.x, b2.y); mma16(acc[0][5], a0, b2.z, b2.w);
            mma16(acc[1][0], a1, b0.x, b0.y); mma16(acc[1][1], a1, b0.z, b0.w);
            mma16(acc[1][2], a1, b1.x, b1.y); mma16(acc[1][3], a1, b1.z, b1.w);
            mma16(acc[1][4], a1, b2.x, b2.y); mma16(acc[1][5], a1, b2.z, b2.w);
        }
        __syncthreads();
    }

    const int gid = lane >> 2, tig = lane & 3;
#pragma unroll
    for (int m = 0; m < 2; ++m) {
        int rr = row0 + (mg * 2 + m) * 16 + gid;
#pragma unroll
        for (int j = 0; j < 6; ++j) {
            int nc = (nh * 6 + j) * 8 + tig * 2;
            float2 bv = *(const float2*)&bias[nc];
            *(float2*)&out[(size_t)rr * 96 + nc] =
                make_float2(acc[m][j][0] + bv.x, acc[m][j][1] + bv.y);
            *(float2*)&out[(size_t)(rr + 8) * 96 + nc] =
                make_float2(acc[m][j][2] + bv.x, acc[m][j][3] + bv.y);
        }
    }
}

// ---------------------------------------------------------------------------
// window attention: one block per (batch, window), 3 heads serial, hd=32
// ---------------------------------------------------------------------------
template <int WS>
__global__ __launch_bounds__(128) void win_attn_k(const float* __restrict__ qkv,
                                                  float* __restrict__ o,
                                                  int Wout, int nw) {
    constexpr int NT = WS * WS;
    __shared__ float sq[NT][33], sk[NT][33], sv[NT][33];
    __shared__ float sS[NT * NT];
    const int b = blockIdx.x / (nw * nw);
    const int win = blockIdx.x % (nw * nw);
    const int wr = win / nw, wc = win % nw;
    const int t = threadIdx.x;
    const int T = Wout * Wout;
    const float scale = 0.17677669529663687f;

    for (int head = 0; head < 3; ++head) {
        for (int idx = t; idx < NT * 32; idx += 128) {
            int p = idx >> 5, c = idx & 31;
            int wi = p / WS, wj = p % WS;
            int r = b * T + (wr * WS + wi) * Wout + wc * WS + wj;
            const float* base = qkv + (size_t)r * 288 + head * 32 + c;
            sq[p][c] = base[0];
            sk[p][c] = base[96];
            sv[p][c] = base[192];
        }
        __syncthreads();
        for (int idx = t; idx < NT * NT; idx += 128) {
            int i = idx / NT, j = idx % NT;
            float s = 0.f;
#pragma unroll
            for (int c = 0; c < 32; ++c) s = fmaf(sq[i][c], sk[j][c], s);
            sS[idx] = s * scale;
        }
        __syncthreads();
        if (t < NT) {
            float m = -1e30f;
            for (int j = 0; j < NT; ++j) m = fmaxf(m, sS[t * NT + j]);
            float Z = 0.f;
            for (int j = 0; j < NT; ++j) {
                float e = __expf(sS[t * NT + j] - m);
                sS[t * NT + j] = e;
                Z += e;
            }
            float inv = 1.f / Z;
            for (int j = 0; j < NT; ++j) sS[t * NT + j] *= inv;
        }
        __syncthreads();
        for (int idx = t; idx < NT * 32; idx += 128) {
            int i = idx >> 5, c = idx & 31;
            float acc = 0.f;
            for (int j = 0; j < NT; ++j) acc = fmaf(sS[i * NT + j], sv[j][c], acc);
            int wi = i / WS, wj = i % WS;
            int r = b * T + (wr * WS + wi) * Wout + wc * WS + wj;
            o[(size_t)r * 96 + head * 32 + c] = acc;
        }
        __syncthreads();
    }
}

// ---------------------------------------------------------------------------
// neighbor gather + LN (scrambled unfold reshape)
// ---------------------------------------------------------------------------
__global__ __launch_bounds__(96) void gather_ln_k(const float* __restrict__ t1,
                                                  const float* __restrict__ t2,
                                                  const float* __restrict__ g,
                                                  const float* __restrict__ bb,
                                                  float* __restrict__ kv) {
    const int b = blockIdx.x / 196, l = blockIdx.x % 196;
    const int i1 = l / 14, j1 = l % 14;
    __shared__ float s1[16 * 97];
    __shared__ float s2[9 * 97];
    __shared__ float red[2][3];
    const int t = threadIdx.x, warp = t >> 5, lane = t & 31;

    for (int p = 0; p < 16; ++p) {
        int ki = p >> 2, kj = p & 3;
        s1[p * 97 + t] = t1[(size_t)((b * 56 + i1 * 4 + ki) * 56 + j1 * 4 + kj) * 96 + t];
    }
    for (int p = 0; p < 9; ++p) {
        int ki = p / 3, kj = p % 3;
        int rr = i1 * 3 + ki - 5, cc = j1 * 3 + kj - 5;
        float v = 0.f;
        if (rr >= 0 && rr < 32 && cc >= 0 && cc < 32)
            v = t2[(size_t)((b * 32 + rr) * 32 + cc) * 96 + t];
        s2[p * 97 + t] = v;
    }
    __syncthreads();
    const float gg = g[t], bv = bb[t];

    for (int k = 0; k < 25; ++k) {
        float v;
        if (k < 16) {
            int F = k * 96 + t;
            int c = F >> 4, rem = F & 15;
            v = s1[rem * 97 + c];
        } else {
            int F = (k - 16) * 96 + t;
            int c = F / 9, rem = F % 9;
            v = s2[rem * 97 + c];
        }
        float s = v, s2s = v * v;
#pragma unroll
        for (int o = 16; o > 0; o >>= 1) {
            s += __shfl_xor_sync(0xffffffffu, s, o);
            s2s += __shfl_xor_sync(0xffffffffu, s2s, o);
        }
        if (lane == 0) { red[0][warp] = s; red[1][warp] = s2s; }
        __syncthreads();
        float S = red[0][0] + red[0][1] + red[0][2];
        float S2 = red[1][0] + red[1][1] + red[1][2];
        float mean = S * (1.f / 96.f);
        float var = fmaf(-mean, mean, S2 * (1.f / 96.f));
        kv[((size_t)blockIdx.x * 25 + k) * 96 + t] = (v - mean) * rsqrtf(var + 1e-5f) * gg + bv;
        __syncthreads();
    }
}

// ---------------------------------------------------------------------------
// cross attention: 1 query vs 25 keys, d=96
// ---------------------------------------------------------------------------
__global__ __launch_bounds__(96) void cross_attn_k(const float* __restrict__ q,
                                                   const float* __restrict__ kbuf,
                                                   const float* __restrict__ vbuf,
                                                   float* __restrict__ o) {
    const int rl = blockIdx.x;
    __shared__ float sk[25][97], sv[25][97], sq[96], ss[25];
    const int t = threadIdx.x;
    sq[t] = q[(size_t)rl * 96 + t];
    for (int k = 0; k < 25; ++k) {
        sk[k][t] = kbuf[((size_t)rl * 25 + k) * 96 + t];
        sv[k][t] = vbuf[((size_t)rl * 25 + k) * 96 + t];
    }
    __syncthreads();
    if (t < 25) {
        float s = 0.f;
        for (int c = 0; c < 96; ++c) s = fmaf(sq[c], sk[t][c], s);
        ss[t] = s * 0.10206207261596575f;
    }
    __syncthreads();
    float m = -1e30f;
#pragma unroll
    for (int k = 0; k < 25; ++k) m = fmaxf(m, ss[k]);
    float Z = 0.f, acc = 0.f;
#pragma unroll
    for (int k = 0; k < 25; ++k) {
        float e = __expf(ss[k] - m);
        Z += e;
        acc = fmaf(e, sv[k][t], acc);
    }
    o[(size_t)rl * 96 + t] = acc / Z;
}

// ---------------------------------------------------------------------------
extern "C" void kernel_launch(void* const* d_in, const int* in_sizes, int n_in,
                              void* d_out, int out_size) {
    const float* x       = (const float*)d_in[0];
    const float* pw[3]   = {(const float*)d_in[1], (const float*)d_in[3], (const float*)d_in[5]};
    const float* pb[3]   = {(const float*)d_in[2], (const float*)d_in[4], (const float*)d_in[6]};
    const float* wa_ln_g = (const float*)d_in[7];
    const float* wa_ln_b = (const float*)d_in[8];
    const float* wa_qkv  = (const float*)d_in[9];
    const float* wa_ow   = (const float*)d_in[10];
    const float* wa_ob   = (const float*)d_in[11];
    const float* ff_ln_g = (const float*)d_in[12];
    const float* ff_ln_b = (const float*)d_in[13];
    const float* ff_w1   = (const float*)d_in[14];
    const float* ff_b1   = (const float*)d_in[15];
    const float* ff_w2   = (const float*)d_in[16];
    const float* ff_b2   = (const float*)d_in[17];
    const float* lnn_g   = (const float*)d_in[18];
    const float* lnn_b   = (const float*)d_in[19];
    const float* ca_wq   = (const float*)d_in[20];
    const float* ca_wk   = (const float*)d_in[21];
    const float* ca_wv   = (const float*)d_in[22];
    const float* ca_wo   = (const float*)d_in[23];
    const float* ca_bo   = (const float*)d_in[24];
    const float* fi_ln_g = (const float*)d_in[25];
    const float* fi_ln_b = (const float*)d_in[26];
    const float* fi_w1   = (const float*)d_in[27];
    const float* fi_b1   = (const float*)d_in[28];
    const float* fi_w2   = (const float*)d_in[29];
    const float* fi_b2   = (const float*)d_in[30];
    float* out = (float*)d_out;

    float *t0, *t1, *t2, *qkv, *ob, *kv, *kk, *vv, *qq, *co;
    cudaGetSymbolAddress((void**)&t0, g_t0);
    cudaGetSymbolAddress((void**)&t1, g_t1);
    cudaGetSymbolAddress((void**)&t2, g_t2);
    cudaGetSymbolAddress((void**)&qkv, g_qkv);
    cudaGetSymbolAddress((void**)&ob, g_ob);
    cudaGetSymbolAddress((void**)&kv, g_kv);
    cudaGetSymbolAddress((void**)&kk, g_k);
    cudaGetSymbolAddress((void**)&vv, g_v);
    cudaGetSymbolAddress((void**)&qq, g_q);
    cudaGetSymbolAddress((void**)&co, g_co);

    // patch merges
    patch_tc<16, 768, 14><<<ROWS0 / 128, 256>>>(x, pw[0], pb[0], t0);
    patch_tc<4, 48, 56><<<ROWS1 / 128, 256>>>(x, pw[1], pb[1], t1);
    patch_tc<7, 147, 32><<<ROWS2 / 128, 256>>>(x, pw[2], pb[2], t2);

    const int rows[3] = {ROWS0, ROWS1, ROWS2};
    float* tb[3] = {t0, t1, t2};
    for (int i = 0; i < 3; ++i) {
        const int R = rows[i];
        float* t = tb[i];
        gemm_tc<true, false, 0><<<dim3(R / 128, 3), 256>>>(
            t, wa_qkv + i * 96 * 288, nullptr, wa_ln_g + i * 96, wa_ln_b + i * 96, nullptr, qkv, 288);
        if (i == 0)      win_attn_k<7><<<64 * 2 * 2, 128>>>(qkv, ob, 14, 2);
        else if (i == 1) win_attn_k<4><<<64 * 14 * 14, 128>>>(qkv, ob, 56, 14);
        else             win_attn_k<4><<<64 * 8 * 8, 128>>>(qkv, ob, 32, 8);
        gemm_tc<false, false, 1><<<dim3(R / 128, 1), 256>>>(
            ob, wa_ow + i * 9216, wa_ob + i * 96, nullptr, nullptr, nullptr, t, 96);
        gemm_tc<true, true, 0><<<dim3(R / 128, 1), 256>>>(
            t, ff_w1 + i * 9216, ff_b1 + i * 96, ff_ln_g + i * 96, ff_ln_b + i * 96, nullptr, ob, 96);
        gemm_tc<false, false, 1><<<dim3(R / 128, 1), 256>>>(
            ob, ff_w2 + i * 9216, ff_b2 + i * 96, nullptr, nullptr, nullptr, t, 96);
    }

    gather_ln_k<<<64 * 196, 96>>>(t1, t2, lnn_g, lnn_b, kv);
    gemm_tc<false, false, 0><<<dim3(KVROWS / 128, 1), 256>>>(kv, ca_wk, nullptr, nullptr, nullptr, nullptr, kk, 96);
    gemm_tc<false, false, 0><<<dim3(KVROWS / 128, 1), 256>>>(kv, ca_wv, nullptr, nullptr, nullptr, nullptr, vv, 96);
    gemm_tc<true, false, 0><<<dim3(ROWS0 / 128, 1), 256>>>(t0, ca_wq, nullptr, lnn_g, lnn_b, nullptr, qq, 96);
    cross_attn_k<<<12544, 96>>>(qq, kk, vv, co);
    gemm_tc<false, false, 2><<<dim3(ROWS0 / 128, 1), 256>>>(co, ca_wo, ca_bo, nullptr, nullptr, t0, out, 96);
    gemm_tc<true, true, 0><<<dim3(ROWS0 / 128, 1), 256>>>(out, fi_w1, fi_b1, fi_ln_g, fi_ln_b, nullptr, co, 96);
    gemm_tc<false, false, 1><<<dim3(ROWS0 / 128, 1), 256>>>(co, fi_w2, fi_b2, nullptr, nullptr, nullptr, out, 96);
}

// round 5
// speedup vs baseline: 2.1326x; 1.1195x over previous
#include <cuda_runtime.h>
#include <cuda_fp16.h>
#include <math.h>

// ---------------------------------------------------------------------------
// MultiScaleCrossAttn — fp16 tensor-core GEMMs, fp16 intermediate storage
// Residual streams stay fp32; everything the GEMMs re-read is fp16.
// ---------------------------------------------------------------------------

#define ROWS0 12544      // 64*14*14
#define ROWS1 200704     // 64*56*56
#define ROWS2 65536      // 64*32*32
#define KVROWS 313600    // 64*196*25

__device__ float g_t0[ROWS0 * 96];
__device__ float g_t1[ROWS1 * 96];
__device__ float g_t2[ROWS2 * 96];
__device__ __align__(16) __half g_qkv[ROWS1 * 288];
__device__ __align__(16) __half g_ob[ROWS1 * 96];
__device__ __align__(16) __half g_kv[KVROWS * 96];
__device__ __align__(16) __half g_k[KVROWS * 96];
__device__ __align__(16) __half g_v[KVROWS * 96];
__device__ __align__(16) __half g_q[ROWS0 * 96];
__device__ __align__(16) __half g_co[ROWS0 * 96];

static constexpr int AS_U4 = 6 * 8 * 32;   // 24KB
static constexpr int BS_U4 = 6 * 6 * 32;   // 18KB

__device__ __forceinline__ unsigned f2h2(float lo, float hi) {
    __half2 h = __floats2half2_rn(lo, hi);
    return *reinterpret_cast<unsigned*>(&h);
}

__device__ __forceinline__ void mma16(float c[4], uint4 a, unsigned b0, unsigned b1) {
    asm volatile(
        "mma.sync.aligned.m16n8k16.row.col.f32.f16.f16.f32 "
        "{%0,%1,%2,%3}, {%4,%5,%6,%7}, {%8,%9}, {%0,%1,%2,%3};\n"
        : "+f"(c[0]), "+f"(c[1]), "+f"(c[2]), "+f"(c[3])
        : "r"(a.x), "r"(a.y), "r"(a.z), "r"(a.w), "r"(b0), "r"(b1));
}

__device__ __forceinline__ float gelu_f(float v) {
    return 0.5f * v * (1.f + erff(v * 0.70710678118654752f));
}

// ---------------------------------------------------------------------------
// K=96 row-GEMM, 256 thr, tile 128x96. TA in {float,__half}, TO in {float,__half}.
// LNF only valid with TA=float. DUAL: blockIdx.y selects (W,out) vs (W2,out2).
// EPI: 0 store, 1 out+=, 2 out=res+val (fp32 res).
// ---------------------------------------------------------------------------
template <class TA, class TO, bool LNF, bool GELU, int EPI, bool DUAL>
__global__ __launch_bounds__(256, 3) void gemm_tc(const TA* __restrict__ A,
                                                  const float* __restrict__ W,
                                                  const float* __restrict__ W2,
                                                  const float* __restrict__ bias,
                                                  const float* __restrict__ lng,
                                                  const float* __restrict__ lnb,
                                                  const float* __restrict__ res,
                                                  TO* __restrict__ out,
                                                  TO* __restrict__ out2, int ldw) {
    constexpr bool TAH = (sizeof(TA) == 2);
    constexpr bool TOH = (sizeof(TO) == 2);
    __shared__ uint4 As4[AS_U4];
    __shared__ uint4 Bs4[BS_U4];
    unsigned* As = (unsigned*)As4;
    unsigned* Bs = (unsigned*)Bs4;
    const int tid = threadIdx.x, lane = tid & 31, warp = tid >> 5;
    const int row0 = blockIdx.x * 128;
    int ncol0 = 0;
    if (DUAL) {
        if (blockIdx.y) { W = W2; out = out2; }
    } else {
        ncol0 = blockIdx.y * 96;
    }

    // ---- stage B (96x96 slice, fp16 frag order) ----
    for (int idx = tid; idx < BS_U4 * 4; idx += 256) {
        int kt = idx / 768;
        int r = idx - kt * 768;
        int jp = r >> 7;
        int r2 = r & 127;
        int ln = r2 >> 2, c = r2 & 3;
        int tig = ln & 3, gid = ln >> 2;
        int n = ncol0 + ((jp << 1) + (c >> 1)) * 8 + gid;
        int k = kt * 16 + 2 * tig + ((c & 1) << 3);
        Bs[idx] = f2h2(__ldg(&W[k * ldw + n]), __ldg(&W[(k + 1) * ldw + n]));
    }

    // ---- stage A: 2 threads per row, 48 contiguous k each ----
    {
        const int row = tid >> 1, sub = tid & 1;
        const int mt = row >> 4, r16 = row & 15;
        const int gid8 = r16 & 7, rowhi = r16 >> 3;
        if constexpr (TAH) {
            const uint4* ap = (const uint4*)((const __half*)A + (size_t)(row0 + row) * 96 + sub * 48);
#pragma unroll
            for (int j = 0; j < 6; ++j) {
                uint4 u = __ldg(&ap[j]);
                unsigned w[4] = {u.x, u.y, u.z, u.w};
#pragma unroll
                for (int wi = 0; wi < 4; ++wi) {
                    int P = sub * 24 + j * 4 + wi;
                    int kt = P >> 3, hi = (P >> 2) & 1, tg = P & 3;
                    As[(((kt * 8 + mt) * 32) + (gid8 << 2) + tg) * 4 + (rowhi | (hi << 1))] = w[wi];
                }
            }
        } else {
            const float* ap = (const float*)A + (size_t)(row0 + row) * 96 + sub * 48;
            float4 vals[12];
#pragma unroll
            for (int j = 0; j < 12; ++j) vals[j] = __ldg((const float4*)(ap + j * 4));
            float mean = 0.f, rstd = 0.f;
            if (LNF) {
                float s = 0.f, s2 = 0.f;
#pragma unroll
                for (int j = 0; j < 12; ++j) {
                    float4 v = vals[j];
                    s += v.x + v.y + v.z + v.w;
                    s2 += v.x * v.x + v.y * v.y + v.z * v.z + v.w * v.w;
                }
                s += __shfl_xor_sync(0xffffffffu, s, 1);
                s2 += __shfl_xor_sync(0xffffffffu, s2, 1);
                mean = s * (1.f / 96.f);
                float var = fmaf(-mean, mean, s2 * (1.f / 96.f));
                rstd = rsqrtf(var + 1e-5f);
            }
#pragma unroll
            for (int j = 0; j < 12; ++j) {
                int k0 = sub * 48 + j * 4;
                float4 v = vals[j];
                if (LNF) {
                    float4 g = __ldg((const float4*)(lng + k0));
                    float4 bb = __ldg((const float4*)(lnb + k0));
                    v.x = (v.x - mean) * rstd * g.x + bb.x;
                    v.y = (v.y - mean) * rstd * g.y + bb.y;
                    v.z = (v.z - mean) * rstd * g.z + bb.z;
                    v.w = (v.w - mean) * rstd * g.w + bb.w;
                }
                int kt = k0 >> 4, kk = k0 & 15;
                int hi = kk >> 3, tig = (kk & 7) >> 1;
                unsigned base = (((kt * 8 + mt) * 32) + (gid8 << 2) + tig) * 4;
                As[base + (rowhi | (hi << 1))] = f2h2(v.x, v.y);
                As[base + 4 + (rowhi | (hi << 1))] = f2h2(v.z, v.w);
            }
        }
    }
    __syncthreads();

    // ---- mainloop: 6 k-steps of 16 ----
    const int mg = warp & 3, nh = warp >> 2;
    float acc[2][6][4];
#pragma unroll
    for (int m = 0; m < 2; ++m)
#pragma unroll
        for (int j = 0; j < 6; ++j)
#pragma unroll
            for (int i = 0; i < 4; ++i) acc[m][j][i] = 0.f;

#pragma unroll
    for (int kt = 0; kt < 6; ++kt) {
        uint4 a0 = As4[(kt * 8 + mg * 2) * 32 + lane];
        uint4 a1 = As4[(kt * 8 + mg * 2 + 1) * 32 + lane];
        uint4 b0 = Bs4[(kt * 6 + nh * 3) * 32 + lane];
        uint4 b1 = Bs4[(kt * 6 + nh * 3 + 1) * 32 + lane];
        uint4 b2 = Bs4[(kt * 6 + nh * 3 + 2) * 32 + lane];
        mma16(acc[0][0], a0, b0.x, b0.y); mma16(acc[0][1], a0, b0.z, b0.w);
        mma16(acc[0][2], a0, b1.x, b1.y); mma16(acc[0][3], a0, b1.z, b1.w);
        mma16(acc[0][4], a0, b2.x, b2.y); mma16(acc[0][5], a0, b2.z, b2.w);
        mma16(acc[1][0], a1, b0.x, b0.y); mma16(acc[1][1], a1, b0.z, b0.w);
        mma16(acc[1][2], a1, b1.x, b1.y); mma16(acc[1][3], a1, b1.z, b1.w);
        mma16(acc[1][4], a1, b2.x, b2.y); mma16(acc[1][5], a1, b2.z, b2.w);
    }

    // ---- epilogue ----
    const int gid = lane >> 2, tig = lane & 3;
#pragma unroll
    for (int m = 0; m < 2; ++m) {
        int rr = row0 + (mg * 2 + m) * 16 + gid;
#pragma unroll
        for (int j = 0; j < 6; ++j) {
            int nc = ncol0 + (nh * 6 + j) * 8 + tig * 2;
            float bx = 0.f, by = 0.f;
            if (bias) {
                float2 bv = *(const float2*)&bias[nc];
                bx = bv.x; by = bv.y;
            }
            float x0 = acc[m][j][0] + bx, x1 = acc[m][j][1] + by;
            float x2 = acc[m][j][2] + bx, x3 = acc[m][j][3] + by;
            if (GELU) { x0 = gelu_f(x0); x1 = gelu_f(x1); x2 = gelu_f(x2); x3 = gelu_f(x3); }
            if constexpr (TOH) {
                __half2* p0 = (__half2*)((__half*)out + (size_t)rr * ldw + nc);
                __half2* p1 = (__half2*)((__half*)out + (size_t)(rr + 8) * ldw + nc);
                *p0 = __floats2half2_rn(x0, x1);
                *p1 = __floats2half2_rn(x2, x3);
            } else {
                float* p0 = (float*)out + (size_t)rr * ldw + nc;
                float* p1 = (float*)out + (size_t)(rr + 8) * ldw + nc;
                if constexpr (EPI == 0) {
                    *(float2*)p0 = make_float2(x0, x1);
                    *(float2*)p1 = make_float2(x2, x3);
                } else if constexpr (EPI == 1) {
                    float2 o0 = *(float2*)p0, o1 = *(float2*)p1;
                    *(float2*)p0 = make_float2(o0.x + x0, o0.y + x1);
                    *(float2*)p1 = make_float2(o1.x + x2, o1.y + x3);
                } else {
                    float2 r0 = *(const float2*)&res[(size_t)rr * 96 + nc];
                    float2 r1 = *(const float2*)&res[(size_t)(rr + 8) * 96 + nc];
                    *(float2*)p0 = make_float2(r0.x + x0, r0.y + x1);
                    *(float2*)p1 = make_float2(r1.x + x2, r1.y + x3);
                }
            }
        }
    }
}

// ---------------------------------------------------------------------------
// patch merge (fp32 in/out), fp16 MMA engine, K chunks of 96
// ---------------------------------------------------------------------------
template <int DF, int KTOT, int WOUT>
__global__ __launch_bounds__(256, 3) void patch_tc(const float* __restrict__ x,
                                                   const float* __restrict__ w,
                                                   const float* __restrict__ bias,
                                                   float* __restrict__ out) {
    constexpr int KPAD = (KTOT + 15) & ~15;
    __shared__ uint4 As4[AS_U4];
    __shared__ uint4 Bs4[BS_U4];
    unsigned* As = (unsigned*)As4;
    unsigned* Bs = (unsigned*)Bs4;
    const int tid = threadIdx.x, lane = tid & 31, warp = tid >> 5;
    const int row0 = blockIdx.x * 128;
    const int T = WOUT * WOUT;
    const int mg = warp & 3, nh = warp >> 2;

    float acc[2][6][4];
#pragma unroll
    for (int m = 0; m < 2; ++m)
#pragma unroll
        for (int j = 0; j < 6; ++j)
#pragma unroll
            for (int i = 0; i < 4; ++i) acc[m][j][i] = 0.f;

    for (int kc = 0; kc < KPAD; kc += 96) {
        const int cl = (KPAD - kc) < 96 ? (KPAD - kc) : 96;
        const int nkt = cl >> 4;

        for (int idx = tid; idx < nkt * 768; idx += 256) {
            int kt = idx / 768;
            int r = idx - kt * 768;
            int jp = r >> 7;
            int r2 = r & 127;
            int ln = r2 >> 2, c = r2 & 3;
            int tig = ln & 3, gid = ln >> 2;
            int n = ((jp << 1) + (c >> 1)) * 8 + gid;
            int k = kc + kt * 16 + 2 * tig + ((c & 1) << 3);
            float lo = (k < KTOT) ? __ldg(&w[k * 96 + n]) : 0.f;
            float hi = (k + 1 < KTOT) ? __ldg(&w[(k + 1) * 96 + n]) : 0.f;
            Bs[idx] = f2h2(lo, hi);
        }
        {
            const int row = tid >> 1, sub = tid & 1;
            const int tok = row0 + row;
            const int b = tok / T, hw = tok - b * T;
            const int h = hw / WOUT, ww = hw - h * WOUT;
            const int mt = row >> 4, r16 = row & 15;
            const int gid8 = r16 & 7, rowhi = r16 >> 3;
#pragma unroll
            for (int j = 0; j < 12; ++j) {
                int k0 = sub * 48 + j * 4;
                if (k0 >= cl) break;
                float v[4];
#pragma unroll
                for (int e = 0; e < 4; ++e) {
                    int f = kc + k0 + e;
                    float vv = 0.f;
                    if (f < KTOT) {
                        int c2 = f / (DF * DF), rem = f - c2 * DF * DF;
                        int ki = rem / DF, kj = rem - ki * DF;
                        vv = __ldg(&x[((b * 3 + c2) * 224 + h * DF + ki) * 224 + ww * DF + kj]);
                    }
                    v[e] = vv;
                }
                int kt = k0 >> 4, kk = k0 & 15;
                int hi = kk >> 3, tig = (kk & 7) >> 1;
                unsigned base = (((kt * 8 + mt) * 32) + (gid8 << 2) + tig) * 4;
                As[base + (rowhi | (hi << 1))] = f2h2(v[0], v[1]);
                As[base + 4 + (rowhi | (hi << 1))] = f2h2(v[2], v[3]);
            }
        }
        __syncthreads();

        for (int kt = 0; kt < nkt; ++kt) {
            uint4 a0 = As4[(kt * 8 + mg * 2) * 32 + lane];
            uint4 a1 = As4[(kt * 8 + mg * 2 + 1) * 32 + lane];
            uint4 b0 = Bs4[(kt * 6 + nh * 3) * 32 + lane];
            uint4 b1 = Bs4[(kt * 6 + nh * 3 + 1) * 32 + lane];
            uint4 b2 = Bs4[(kt * 6 + nh * 3 + 2) * 32 + lane];
            mma16(acc[0][0], a0, b0.x, b0.y); mma16(acc[0][1], a0, b0.z, b0.w);
            mma16(acc[0][2], a0, b1.x, b1.y); mma16(acc[0][3], a0, b1.z, b1.w);
            mma16(acc[0][4], a0, b2.x, b2.y); mma16(acc[0][5], a0, b2.z, b2.w);
            mma16(acc[1][0], a1, b0.x, b0.y); mma16(acc[1][1], a1, b0.z, b0.w);
            mma16(acc[1][2], a1, b1.x, b1.y); mma16(acc[1][3], a1, b1.z, b1.w);
            mma16(acc[1][4], a1, b2.x, b2.y); mma16(acc[1][5], a1, b2.z, b2.w);
        }
        __syncthreads();
    }

    const int gid = lane >> 2, tig = lane & 3;
#pragma unroll
    for (int m = 0; m < 2; ++m) {
        int rr = row0 + (mg * 2 + m) * 16 + gid;
#pragma unroll
        for (int j = 0; j < 6; ++j) {
            int nc = (nh * 6 + j) * 8 + tig * 2;
            float2 bv = *(const float2*)&bias[nc];
            *(float2*)&out[(size_t)rr * 96 + nc] =
                make_float2(acc[m][j][0] + bv.x, acc[m][j][1] + bv.y);
            *(float2*)&out[(size_t)(rr + 8) * 96 + nc] =
                make_float2(acc[m][j][2] + bv.x, acc[m][j][3] + bv.y);
        }
    }
}

// ---------------------------------------------------------------------------
// window attention: fp16 in/out, fp32 math
// ---------------------------------------------------------------------------
template <int WS>
__global__ __launch_bounds__(128) void win_attn_k(const __half* __restrict__ qkv,
                                                  __half* __restrict__ o,
                                                  int Wout, int nw) {
    constexpr int NT = WS * WS;
    __shared__ float sq[NT][33], sk[NT][33], sv[NT][33];
    __shared__ float sS[NT * NT];
    const int b = blockIdx.x / (nw * nw);
    const int win = blockIdx.x % (nw * nw);
    const int wr = win / nw, wc = win % nw;
    const int t = threadIdx.x;
    const int T = Wout * Wout;
    const float scale = 0.17677669529663687f;

    for (int head = 0; head < 3; ++head) {
        for (int idx = t; idx < NT * 32; idx += 128) {
            int p = idx >> 5, c = idx & 31;
            int wi = p / WS, wj = p % WS;
            int r = b * T + (wr * WS + wi) * Wout + wc * WS + wj;
            const __half* base = qkv + (size_t)r * 288 + head * 32 + c;
            sq[p][c] = __half2float(base[0]);
            sk[p][c] = __half2float(base[96]);
            sv[p][c] = __half2float(base[192]);
        }
        __syncthreads();
        for (int idx = t; idx < NT * NT; idx += 128) {
            int i = idx / NT, j = idx % NT;
            float s = 0.f;
#pragma unroll
            for (int c = 0; c < 32; ++c) s = fmaf(sq[i][c], sk[j][c], s);
            sS[idx] = s * scale;
        }
        __syncthreads();
        if (t < NT) {
            float m = -1e30f;
            for (int j = 0; j < NT; ++j) m = fmaxf(m, sS[t * NT + j]);
            float Z = 0.f;
            for (int j = 0; j < NT; ++j) {
                float e = __expf(sS[t * NT + j] - m);
                sS[t * NT + j] = e;
                Z += e;
            }
            float inv = 1.f / Z;
            for (int j = 0; j < NT; ++j) sS[t * NT + j] *= inv;
        }
        __syncthreads();
        for (int idx = t; idx < NT * 32; idx += 128) {
            int i = idx >> 5, c = idx & 31;
            float acc = 0.f;
            for (int j = 0; j < NT; ++j) acc = fmaf(sS[i * NT + j], sv[j][c], acc);
            int wi = i / WS, wj = i % WS;
            int r = b * T + (wr * WS + wi) * Wout + wc * WS + wj;
            o[(size_t)r * 96 + head * 32 + c] = __float2half(acc);
        }
        __syncthreads();
    }
}

// ---------------------------------------------------------------------------
// neighbor gather + LN (scrambled unfold reshape), fp32 in, fp16 out
// ---------------------------------------------------------------------------
__global__ __launch_bounds__(96) void gather_ln_k(const float* __restrict__ t1,
                                                  const float* __restrict__ t2,
                                                  const float* __restrict__ g,
                                                  const float* __restrict__ bb,
                                                  __half* __restrict__ kv) {
    const int b = blockIdx.x / 196, l = blockIdx.x % 196;
    const int i1 = l / 14, j1 = l % 14;
    __shared__ float s1[16 * 97];
    __shared__ float s2[9 * 97];
    __shared__ float red[2][3];
    const int t = threadIdx.x, warp = t >> 5, lane = t & 31;

    for (int p = 0; p < 16; ++p) {
        int ki = p >> 2, kj = p & 3;
        s1[p * 97 + t] = t1[(size_t)((b * 56 + i1 * 4 + ki) * 56 + j1 * 4 + kj) * 96 + t];
    }
    for (int p = 0; p < 9; ++p) {
        int ki = p / 3, kj = p % 3;
        int rr = i1 * 3 + ki - 5, cc = j1 * 3 + kj - 5;
        float v = 0.f;
        if (rr >= 0 && rr < 32 && cc >= 0 && cc < 32)
            v = t2[(size_t)((b * 32 + rr) * 32 + cc) * 96 + t];
        s2[p * 97 + t] = v;
    }
    __syncthreads();
    const float gg = g[t], bv = bb[t];

    for (int k = 0; k < 25; ++k) {
        float v;
        if (k < 16) {
            int F = k * 96 + t;
            int c = F >> 4, rem = F & 15;
            v = s1[rem * 97 + c];
        } else {
            int F = (k - 16) * 96 + t;
            int c = F / 9, rem = F % 9;
            v = s2[rem * 97 + c];
        }
        float s = v, s2s = v * v;
#pragma unroll
        for (int o = 16; o > 0; o >>= 1) {
            s += __shfl_xor_sync(0xffffffffu, s, o);
            s2s += __shfl_xor_sync(0xffffffffu, s2s, o);
        }
        if (lane == 0) { red[0][warp] = s; red[1][warp] = s2s; }
        __syncthreads();
        float S = red[0][0] + red[0][1] + red[0][2];
        float S2 = red[1][0] + red[1][1] + red[1][2];
        float mean = S * (1.f / 96.f);
        float var = fmaf(-mean, mean, S2 * (1.f / 96.f));
        kv[((size_t)blockIdx.x * 25 + k) * 96 + t] =
            __float2half((v - mean) * rsqrtf(var + 1e-5f) * gg + bv);
        __syncthreads();
    }
}

// ---------------------------------------------------------------------------
// cross attention: fp16 in/out, fp32 math
// ---------------------------------------------------------------------------
__global__ __launch_bounds__(96) void cross_attn_k(const __half* __restrict__ q,
                                                   const __half* __restrict__ kbuf,
                                                   const __half* __restrict__ vbuf,
                                                   __half* __restrict__ o) {
    const int rl = blockIdx.x;
    __shared__ float sk[25][97], sv[25][97], sq[96], ss[25];
    const int t = threadIdx.x;
    sq[t] = __half2float(q[(size_t)rl * 96 + t]);
    for (int k = 0; k < 25; ++k) {
        sk[k][t] = __half2float(kbuf[((size_t)rl * 25 + k) * 96 + t]);
        sv[k][t] = __half2float(vbuf[((size_t)rl * 25 + k) * 96 + t]);
    }
    __syncthreads();
    if (t < 25) {
        float s = 0.f;
        for (int c = 0; c < 96; ++c) s = fmaf(sq[c], sk[t][c], s);
        ss[t] = s * 0.10206207261596575f;
    }
    __syncthreads();
    float m = -1e30f;
#pragma unroll
    for (int k = 0; k < 25; ++k) m = fmaxf(m, ss[k]);
    float Z = 0.f, acc = 0.f;
#pragma unroll
    for (int k = 0; k < 25; ++k) {
        float e = __expf(ss[k] - m);
        Z += e;
        acc = fmaf(e, sv[k][t], acc);
    }
    o[(size_t)rl * 96 + t] = __float2half(acc / Z);
}

// ---------------------------------------------------------------------------
extern "C" void kernel_launch(void* const* d_in, const int* in_sizes, int n_in,
                              void* d_out, int out_size) {
    const float* x       = (const float*)d_in[0];
    const float* pw[3]   = {(const float*)d_in[1], (const float*)d_in[3], (const float*)d_in[5]};
    const float* pb[3]   = {(const float*)d_in[2], (const float*)d_in[4], (const float*)d_in[6]};
    const float* wa_ln_g = (const float*)d_in[7];
    const float* wa_ln_b = (const float*)d_in[8];
    const float* wa_qkv  = (const float*)d_in[9];
    const float* wa_ow   = (const float*)d_in[10];
    const float* wa_ob   = (const float*)d_in[11];
    const float* ff_ln_g = (const float*)d_in[12];
    const float* ff_ln_b = (const float*)d_in[13];
    const float* ff_w1   = (const float*)d_in[14];
    const float* ff_b1   = (const float*)d_in[15];
    const float* ff_w2   = (const float*)d_in[16];
    const float* ff_b2   = (const float*)d_in[17];
    const float* lnn_g   = (const float*)d_in[18];
    const float* lnn_b   = (const float*)d_in[19];
    const float* ca_wq   = (const float*)d_in[20];
    const float* ca_wk   = (const float*)d_in[21];
    const float* ca_wv   = (const float*)d_in[22];
    const float* ca_wo   = (const float*)d_in[23];
    const float* ca_bo   = (const float*)d_in[24];
    const float* fi_ln_g = (const float*)d_in[25];
    const float* fi_ln_b = (const float*)d_in[26];
    const float* fi_w1   = (const float*)d_in[27];
    const float* fi_b1   = (const float*)d_in[28];
    const float* fi_w2   = (const float*)d_in[29];
    const float* fi_b2   = (const float*)d_in[30];
    float* out = (float*)d_out;

    float *t0, *t1, *t2;
    __half *qkv, *ob, *kv, *kk, *vv, *qq, *co;
    cudaGetSymbolAddress((void**)&t0, g_t0);
    cudaGetSymbolAddress((void**)&t1, g_t1);
    cudaGetSymbolAddress((void**)&t2, g_t2);
    cudaGetSymbolAddress((void**)&qkv, g_qkv);
    cudaGetSymbolAddress((void**)&ob, g_ob);
    cudaGetSymbolAddress((void**)&kv, g_kv);
    cudaGetSymbolAddress((void**)&kk, g_k);
    cudaGetSymbolAddress((void**)&vv, g_v);
    cudaGetSymbolAddress((void**)&qq, g_q);
    cudaGetSymbolAddress((void**)&co, g_co);

    // patch merges (fp32 residual streams)
    patch_tc<16, 768, 14><<<ROWS0 / 128, 256>>>(x, pw[0], pb[0], t0);
    patch_tc<4, 48, 56><<<ROWS1 / 128, 256>>>(x, pw[1], pb[1], t1);
    patch_tc<7, 147, 32><<<ROWS2 / 128, 256>>>(x, pw[2], pb[2], t2);

    const int rows[3] = {ROWS0, ROWS1, ROWS2};
    float* tb[3] = {t0, t1, t2};
    for (int i = 0; i < 3; ++i) {
        const int R = rows[i];
        float* t = tb[i];
        // qkv(fp16) = LN(t) @ Wqkv
        gemm_tc<float, __half, true, false, 0, false><<<dim3(R / 128, 3), 256>>>(
            t, wa_qkv + i * 96 * 288, nullptr, nullptr,
            wa_ln_g + i * 96, wa_ln_b + i * 96, nullptr, qkv, nullptr, 288);
        if (i == 0)      win_attn_k<7><<<64 * 2 * 2, 128>>>(qkv, ob, 14, 2);
        else if (i == 1) win_attn_k<4><<<64 * 14 * 14, 128>>>(qkv, ob, 56, 14);
        else             win_attn_k<4><<<64 * 8 * 8, 128>>>(qkv, ob, 32, 8);
        // t(fp32) += attn_out(fp16) @ Wo + bo
        gemm_tc<__half, float, false, false, 1, false><<<dim3(R / 128, 1), 256>>>(
            ob, wa_ow + i * 9216, nullptr, wa_ob + i * 96,
            nullptr, nullptr, nullptr, t, nullptr, 96);
        // h(fp16) = gelu(LN(t) @ W1 + b1)
        gemm_tc<float, __half, true, true, 0, false><<<dim3(R / 128, 1), 256>>>(
            t, ff_w1 + i * 9216, nullptr, ff_b1 + i * 96,
            ff_ln_g + i * 96, ff_ln_b + i * 96, nullptr, ob, nullptr, 96);
        // t(fp32) += h @ W2 + b2
        gemm_tc<__half, float, false, false, 1, false><<<dim3(R / 128, 1), 256>>>(
            ob, ff_w2 + i * 9216, nullptr, ff_b2 + i * 96,
            nullptr, nullptr, nullptr, t, nullptr, 96);
    }

    // neighbor gather + LN -> kv(fp16)
    gather_ln_k<<<64 * 196, 96>>>(t1, t2, lnn_g, lnn_b, kv);
    // k/v projections in ONE dual launch (fp16 in/out)
    gemm_tc<__half, __half, false, false, 0, true><<<dim3(KVROWS / 128, 2), 256>>>(
        kv, ca_wk, ca_wv, nullptr, nullptr, nullptr, nullptr, kk, vv, 96);
    // q(fp16) = LN(t0) @ Wq
    gemm_tc<float, __half, true, false, 0, false><<<dim3(ROWS0 / 128, 1), 256>>>(
        t0, ca_wq, nullptr, nullptr, lnn_g, lnn_b, nullptr, qq, nullptr, 96);
    // cross attention
    cross_attn_k<<<12544, 96>>>(qq, kk, vv, co);
    // out(fp32) = t0 + co @ Wo + bo
    gemm_tc<__half, float, false, false, 2, false><<<dim3(ROWS0 / 128, 1), 256>>>(
        co, ca_wo, nullptr, ca_bo, nullptr, nullptr, t0, out, nullptr, 96);
    // out += gelu(LN(out) @ w1 + b1) @ w2 + b2
    gemm_tc<float, __half, true, true, 0, false><<<dim3(ROWS0 / 128, 1), 256>>>(
        out, fi_w1, nullptr, fi_b1, fi_ln_g, fi_ln_b, nullptr, ob, nullptr, 96);
    gemm_tc<__half, float, false, false, 1, false><<<dim3(ROWS0 / 128, 1), 256>>>(
        ob, fi_w2, nullptr, fi_b2, nullptr, nullptr, nullptr, out, nullptr, 96);
}